// round 11
// baseline (speedup 1.0000x reference)
#include <cuda_runtime.h>
#include <cuda_bf16.h>
#include <math.h>
#include <stdint.h>

#define D_DIM 2048
#define EMB   256
#define E_EXP 64
#define MAX_N 65536
#define THETA 2e-4f
#define MAXFLAG 8192
#define RB 8

// ---------------------------------------------------------------------------
// Device-global scratch
// ---------------------------------------------------------------------------
__device__ float g_proj[(size_t)MAX_N * EMB];
__device__ float g_embn[EMB * E_EXP];
__device__ int   g_nflag;
__device__ int   g_flagrows[MAXFLAG];

__device__ __align__(128) unsigned char g_whi[(size_t)EMB * D_DIM * 2];
__device__ __align__(128) unsigned char g_wlo[(size_t)EMB * D_DIM * 2];
__device__ __align__(128) unsigned char g_ebhi[32768];
__device__ __align__(128) unsigned char g_eblo[32768];

// ---------------------------------------------------------------------------
// Base-ISA PTX helpers
// ---------------------------------------------------------------------------
__device__ __forceinline__ uint32_t smem_u32(const void* p) {
    uint32_t a;
    asm("{ .reg .u64 t; cvta.to.shared.u64 t, %1; cvt.u32.u64 %0, t; }"
        : "=r"(a) : "l"(p));
    return a;
}
__device__ __forceinline__ void cp16(uint32_t s, const void* g) {
    asm volatile("cp.async.cg.shared.global [%0], [%1], 16;"
                 :: "r"(s), "l"(g) : "memory");
}
#define CP_COMMIT() asm volatile("cp.async.commit_group;" ::: "memory")
#define CP_WAIT(n)  asm volatile("cp.async.wait_group %0;" :: "n"(n) : "memory")

#define LDSM4(R, a)                                                            \
    asm volatile("ldmatrix.sync.aligned.m8n8.x4.shared.b16 {%0,%1,%2,%3}, [%4];" \
        : "=r"((R)[0]), "=r"((R)[1]), "=r"((R)[2]), "=r"((R)[3]) : "r"(a))

#define MMA16816(C, A, B0, B1)                                                 \
    asm volatile(                                                              \
        "mma.sync.aligned.m16n8k16.row.col.f32.bf16.bf16.f32 "                 \
        "{%0,%1,%2,%3}, {%4,%5,%6,%7}, {%8,%9}, {%0,%1,%2,%3};"                \
        : "+f"((C)[0]), "+f"((C)[1]), "+f"((C)[2]), "+f"((C)[3])               \
        : "r"((A)[0]), "r"((A)[1]), "r"((A)[2]), "r"((A)[3]),                  \
          "r"(B0), "r"(B1))

__device__ __forceinline__ uint32_t swz(int r, int c) {
    return (uint32_t)(r * 64 + ((c ^ ((r >> 1) & 3)) * 16));
}

// ---------------------------------------------------------------------------
// split + transpose W [2048,256] -> [256][2048] (hi, lo) bf16
// ---------------------------------------------------------------------------
__global__ void __launch_bounds__(256) splitw_kernel(const float* __restrict__ W) {
    int idx = blockIdx.x * 256 + threadIdx.x;
    int n = idx >> 8;
    int k = (idx & 255) << 3;

    union { __nv_bfloat16 h[8]; uint4 v; } ph, pl;
#pragma unroll
    for (int i = 0; i < 8; i++) {
        float f = W[(size_t)(k + i) * EMB + n];
        __nv_bfloat16 hi = __float2bfloat16(f);
        ph.h[i] = hi;
        pl.h[i] = __float2bfloat16(f - __bfloat162float(hi));
    }
    size_t off = (size_t)n * (D_DIM * 2) + (size_t)k * 2;
    *(uint4*)(g_whi + off) = ph.v;
    *(uint4*)(g_wlo + off) = pl.v;
}

// ---------------------------------------------------------------------------
// normalize expert_emb columns; emit expert-major split emb_n^T (swizzled)
// ---------------------------------------------------------------------------
__global__ void embn_kernel(const float* __restrict__ emb) {
    __shared__ float red[EMB];
    int e = blockIdx.x;
    int k = threadIdx.x;
    if (e == 0 && k == 0) g_nflag = 0;
    float v = emb[(size_t)k * E_EXP + e];
    red[k] = v * v;
    __syncthreads();
#pragma unroll
    for (int s = 128; s > 0; s >>= 1) {
        if (k < s) red[k] += red[k + s];
        __syncthreads();
    }
    float inv = 1.0f / sqrtf(red[0] + 1e-12f);
    float vn = v * inv;
    g_embn[(size_t)k * E_EXP + e] = vn;

    __nv_bfloat16 hi = __float2bfloat16(vn);
    __nv_bfloat16 lo = __float2bfloat16(vn - __bfloat162float(hi));
    uint32_t addr = (uint32_t)(k >> 5) * 4096 + swz(e, (k & 31) >> 3) + (k & 7) * 2;
    *(__nv_bfloat16*)(g_ebhi + addr) = hi;
    *(__nv_bfloat16*)(g_eblo + addr) = lo;
}

// ---------------------------------------------------------------------------
// GEMM v4: CTA tile 128x256 (full N), 512 threads / 16 warps, warp tile
// 32x64, 3-stage pipeline, fused A split. x read exactly once from DRAM.
// ---------------------------------------------------------------------------
#define NSTAGE      3
#define STAGE_BYTES 49152u    // Ahi 8K | Alo 8K | Bhi 16K | Blo 16K
#define OFF_ALO     8192u
#define OFF_BHI     16384u
#define OFF_BLO     32768u
#define NKT         (D_DIM / 32)   // 64

__global__ void __launch_bounds__(512, 1) mma_gemm_kernel(
        const float* __restrict__ x, int M) {
    extern __shared__ __align__(128) unsigned char smem[];
    uint32_t sb = smem_u32(smem);
    int tid  = threadIdx.x;
    int lane = tid & 31;
    int w    = tid >> 5;     // 0..15
    int mw   = w & 3;        // M slice (32 rows)
    int nw   = w >> 2;       // N slice (64 cols)

    size_t bm = (size_t)blockIdx.x * 128;

    // A loader: thread t -> row t/4 (0..127), 16B chunk t&3
    int alr = tid >> 2;
    int alq = tid & 3;
    const float* xrow = x + (bm + alr) * D_DIM + alq * 8;
    // B loader: thread t -> row t/2 (0..255), chunks (t&1)*2 + {0,1}
    int blr = tid >> 1;
    int blq = (tid & 1) * 2;
    size_t brow = (size_t)blr * (D_DIM * 2) + (size_t)blq * 16;

    float f[8];
    auto ldga = [&](int kt) {
        const float4* p = (const float4*)(xrow + (size_t)kt * 32);
        float4 v0 = p[0], v1 = p[1];
        f[0] = v0.x; f[1] = v0.y; f[2] = v0.z; f[3] = v0.w;
        f[4] = v1.x; f[5] = v1.y; f[6] = v1.z; f[7] = v1.w;
    };
    auto stsa = [&](int s) {
        union { __nv_bfloat16 h[8]; uint4 v; } ph, pl;
#pragma unroll
        for (int i = 0; i < 8; i++) {
            __nv_bfloat16 hi = __float2bfloat16(f[i]);
            ph.h[i] = hi;
            pl.h[i] = __float2bfloat16(f[i] - __bfloat162float(hi));
        }
        uint32_t so = (uint32_t)s * STAGE_BYTES + swz(alr, alq);
        *(uint4*)(smem + so) = ph.v;
        *(uint4*)(smem + so + OFF_ALO) = pl.v;
    };
    auto cpb = [&](int kt, int s) {
        uint32_t st = sb + (uint32_t)s * STAGE_BYTES;
        size_t go = brow + (size_t)kt * 64;
        uint32_t so0 = swz(blr, blq);
        uint32_t so1 = swz(blr, blq + 1);
        cp16(st + OFF_BHI + so0, g_whi + go);
        cp16(st + OFF_BHI + so1, g_whi + go + 16);
        cp16(st + OFF_BLO + so0, g_wlo + go);
        cp16(st + OFF_BLO + so1, g_wlo + go + 16);
        CP_COMMIT();
    };

    // prologue
    ldga(0); stsa(0); cpb(0, 0);
    ldga(1); stsa(1); cpb(1, 1);
    ldga(2);

    float acc[2][8][4];
#pragma unroll
    for (int i = 0; i < 2; i++)
#pragma unroll
        for (int j = 0; j < 8; j++)
#pragma unroll
            for (int q = 0; q < 4; q++) acc[i][j][q] = 0.0f;

    int a_r  = lane & 15;
    int a_cb = lane >> 4;
    int b_r  = (lane & 7) + ((lane >> 4) & 1) * 8;
    int b_cb = (lane >> 3) & 1;

    for (int kt = 0; kt < NKT; kt++) {
        CP_WAIT(1);
        __syncthreads();

        int nx = kt + 2;
        bool pf = nx < NKT;
        if (pf) cpb(nx, nx % NSTAGE);
        else    CP_COMMIT();

        uint32_t st = sb + (uint32_t)(kt % NSTAGE) * STAGE_BYTES;

#pragma unroll
        for (int kh = 0; kh < 2; kh++) {
            uint32_t ahi[2][4], alo[2][4];
#pragma unroll
            for (int i = 0; i < 2; i++) {
                int r = mw * 32 + i * 16 + a_r;
                uint32_t ad = st + swz(r, 2 * kh + a_cb);
                LDSM4(ahi[i], ad);
                LDSM4(alo[i], ad + OFF_ALO);
            }
#pragma unroll
            for (int h = 0; h < 2; h++) {     // 32-col halves (reg pressure)
                uint32_t bhi[2][4], blo[2][4];
#pragma unroll
                for (int j2 = 0; j2 < 2; j2++) {
                    int r = nw * 64 + h * 32 + j2 * 16 + b_r;
                    uint32_t ad = st + OFF_BHI + swz(r, 2 * kh + b_cb);
                    LDSM4(bhi[j2], ad);
                    LDSM4(blo[j2], ad + (OFF_BLO - OFF_BHI));
                }
#pragma unroll
                for (int i = 0; i < 2; i++) {
#pragma unroll
                    for (int j = 0; j < 4; j++) {
                        uint32_t* bh = &bhi[j >> 1][(j & 1) * 2];
                        uint32_t* bl = &blo[j >> 1][(j & 1) * 2];
                        MMA16816(acc[i][h * 4 + j], ahi[i], bh[0], bh[1]);
                        MMA16816(acc[i][h * 4 + j], ahi[i], bl[0], bl[1]);
                        MMA16816(acc[i][h * 4 + j], alo[i], bh[0], bh[1]);
                    }
                }
            }
        }
        if (pf) {
            stsa(nx % NSTAGE);      // stage (kt-1)%3: safe (top sync passed)
            if (kt + 3 < NKT) ldga(kt + 3);
        }
    }

#pragma unroll
    for (int i = 0; i < 2; i++) {
#pragma unroll
        for (int j = 0; j < 8; j++) {
            size_t r0 = bm + mw * 32 + i * 16 + (lane >> 2);
            int col = nw * 64 + j * 8 + 2 * (lane & 3);
            *(float2*)&g_proj[r0 * EMB + col] =
                make_float2(acc[i][j][0], acc[i][j][1]);
            *(float2*)&g_proj[(r0 + 8) * EMB + col] =
                make_float2(acc[i][j][2], acc[i][j][3]);
        }
    }
}

// ---------------------------------------------------------------------------
// Gate kernel v2 (unchanged): tensor-core cos, one CTA = 64 rows
// ---------------------------------------------------------------------------
#define SM_BHI  0u
#define SM_BLO  32768u
#define SM_AHI  65536u
#define SM_ALO  98304u
#define SM_SCOS 131072u            // float[64][66]
#define SM_SSUM 147968u            // float[64]
#define GATE_SMEM 148224u

__global__ void __launch_bounds__(256) gate_kernel(
        const float* __restrict__ tptr, float* __restrict__ out, int M) {
    extern __shared__ __align__(128) unsigned char smem[];
    uint32_t sb = smem_u32(smem);
    float* scos = (float*)(smem + SM_SCOS);
    float* ssum = (float*)(smem + SM_SSUM);

    int t = threadIdx.x;
    int lane = t & 31;
    int w = t >> 5;

    {
        const uint4* shi = (const uint4*)g_ebhi;
        const uint4* slo = (const uint4*)g_eblo;
        uint4* dhi = (uint4*)(smem + SM_BHI);
        uint4* dlo = (uint4*)(smem + SM_BLO);
#pragma unroll
        for (int i = 0; i < 8; i++) {
            dhi[t + i * 256] = shi[t + i * 256];
            dlo[t + i * 256] = slo[t + i * 256];
        }
    }

    int gr0 = blockIdx.x * 64;
    int lr = t >> 2;
    int q  = t & 3;

    float4 f[16];
    const float4* xp = (const float4*)(g_proj + (size_t)(gr0 + lr) * EMB + q * 64);
    float ss = 0.0f;
#pragma unroll
    for (int i = 0; i < 16; i++) {
        float4 v = xp[i];
        f[i] = v;
        ss += v.x * v.x + v.y * v.y + v.z * v.z + v.w * v.w;
    }
    ss += __shfl_xor_sync(0xffffffffu, ss, 1);
    ss += __shfl_xor_sync(0xffffffffu, ss, 2);
    if (q == 0) ssum[lr] = ss;

#pragma unroll
    for (int j = 0; j < 8; j++) {
        float fv[8] = {f[2*j].x, f[2*j].y, f[2*j].z, f[2*j].w,
                       f[2*j+1].x, f[2*j+1].y, f[2*j+1].z, f[2*j+1].w};
        union { __nv_bfloat16 h[8]; uint4 v; } ph, pl;
#pragma unroll
        for (int i = 0; i < 8; i++) {
            __nv_bfloat16 hi = __float2bfloat16(fv[i]);
            ph.h[i] = hi;
            pl.h[i] = __float2bfloat16(fv[i] - __bfloat162float(hi));
        }
        uint32_t so = (uint32_t)(q * 2 + (j >> 2)) * 4096 + swz(lr, j & 3);
        *(uint4*)(smem + SM_AHI + so) = ph.v;
        *(uint4*)(smem + SM_ALO + so) = pl.v;
    }
    __syncthreads();

    int mw = w & 3;
    int nw = w >> 2;
    float acc[4][4];
#pragma unroll
    for (int j = 0; j < 4; j++)
#pragma unroll
        for (int qq = 0; qq < 4; qq++) acc[j][qq] = 0.0f;

    int a_r = lane & 15;
    int a_cb = lane >> 4;
    int b_r = (lane & 7) + ((lane >> 4) & 1) * 8;
    int b_cb = (lane >> 3) & 1;

#pragma unroll
    for (int kc = 0; kc < 8; kc++) {
#pragma unroll
        for (int kh = 0; kh < 2; kh++) {
            uint32_t ahi[4], alo[4], bhi[2][4], blo[2][4];
            uint32_t ca = SM_AHI + (uint32_t)kc * 4096 + swz(mw * 16 + a_r, 2 * kh + a_cb);
            LDSM4(ahi, sb + ca);
            LDSM4(alo, sb + ca + (SM_ALO - SM_AHI));
#pragma unroll
            for (int j2 = 0; j2 < 2; j2++) {
                uint32_t cb = SM_BHI + (uint32_t)kc * 4096
                            + swz(nw * 32 + j2 * 16 + b_r, 2 * kh + b_cb);
                LDSM4(bhi[j2], sb + cb);
                LDSM4(blo[j2], sb + cb + (SM_BLO - SM_BHI));
            }
#pragma unroll
            for (int j = 0; j < 4; j++) {
                uint32_t* bh = &bhi[j >> 1][(j & 1) * 2];
                uint32_t* bl = &blo[j >> 1][(j & 1) * 2];
                MMA16816(acc[j], ahi, bh[0], bh[1]);
                MMA16816(acc[j], ahi, bl[0], bl[1]);
                MMA16816(acc[j], alo, bh[0], bh[1]);
            }
        }
    }

    int r0 = mw * 16 + (lane >> 2);
    float inv0 = 1.0f / sqrtf(ssum[r0] + 1e-12f);
    float inv1 = 1.0f / sqrtf(ssum[r0 + 8] + 1e-12f);
#pragma unroll
    for (int j = 0; j < 4; j++) {
        int col = nw * 32 + j * 8 + (lane & 3) * 2;
        scos[r0 * 66 + col]       = acc[j][0] * inv0;
        scos[r0 * 66 + col + 1]   = acc[j][1] * inv0;
        scos[(r0 + 8) * 66 + col]     = acc[j][2] * inv1;
        scos[(r0 + 8) * 66 + col + 1] = acc[j][3] * inv1;
    }
    __syncthreads();

    float temp = tptr[0];
    size_t nM = (size_t)M;
    float* out_ew  = out;
    float* out_ti  = out + nM * 64;
    float* out_lg  = out + nM * 66;
    float* out_cs  = out + nM * 130;
    float* out_raw = out + nM * 194;

#pragma unroll
    for (int r8 = 0; r8 < 8; r8++) {
        int row = w * 8 + r8;
        int gr = gr0 + row;
        float c0 = scos[row * 66 + lane];
        float c1 = scos[row * 66 + lane + 32];
        float l0 = c0 * temp;
        float l1 = c1 * temp;

        float bv = l0; int bi = lane;
        if (l1 > bv) { bv = l1; bi = lane + 32; }
#pragma unroll
        for (int off = 16; off > 0; off >>= 1) {
            float ov = __shfl_xor_sync(0xffffffffu, bv, off);
            int   oi = __shfl_xor_sync(0xffffffffu, bi, off);
            if (ov > bv || (ov == bv && oi < bi)) { bv = ov; bi = oi; }
        }
        float t1v = bv; int t1i = bi;

        float m0 = (lane == t1i)      ? -INFINITY : l0;
        float m1 = (lane + 32 == t1i) ? -INFINITY : l1;
        bv = m0; bi = lane;
        if (m1 > bv || (m1 == bv && (lane + 32) < bi)) { bv = m1; bi = lane + 32; }
#pragma unroll
        for (int off = 16; off > 0; off >>= 1) {
            float ov = __shfl_xor_sync(0xffffffffu, bv, off);
            int   oi = __shfl_xor_sync(0xffffffffu, bi, off);
            if (ov > bv || (ov == bv && oi < bi)) { bv = ov; bi = oi; }
        }
        float t2v = bv; int t2i = bi;

        float p0 = (lane == t1i || lane == t2i) ? -INFINITY : l0;
        float p1 = (lane + 32 == t1i || lane + 32 == t2i) ? -INFINITY : l1;
        float t3v = fmaxf(p0, p1);
#pragma unroll
        for (int off = 16; off > 0; off >>= 1)
            t3v = fmaxf(t3v, __shfl_xor_sync(0xffffffffu, t3v, off));

        float ex0 = expf(l0 - t1v);
        float ex1 = expf(l1 - t1v);
        float tot = ex0 + ex1;
#pragma unroll
        for (int off = 16; off > 0; off >>= 1)
            tot += __shfl_xor_sync(0xffffffffu, tot, off);
        float r0s = ex0 / tot;
        float r1s = ex1 / tot;

        float eT = expf(t2v - t1v);
        float denom = 1.0f + eT;
        float w1 = 1.0f / denom;
        float w2 = eT / denom;
        float ew0 = (lane == t1i) ? w1 : ((lane == t2i) ? w2 : 0.0f);
        float ew1 = (lane + 32 == t1i) ? w1 : ((lane + 32 == t2i) ? w2 : 0.0f);

        size_t ro = (size_t)gr * 64;
        out_ew[ro + lane]       = ew0;
        out_ew[ro + lane + 32]  = ew1;
        out_lg[ro + lane]       = l0;
        out_lg[ro + lane + 32]  = l1;
        out_cs[ro + lane]       = c0;
        out_cs[ro + lane + 32]  = c1;
        out_raw[ro + lane]      = r0s;
        out_raw[ro + lane + 32] = r1s;
        if (lane == 0) {
            out_ti[(size_t)gr * 2]     = (float)t1i;
            out_ti[(size_t)gr * 2 + 1] = (float)t2i;
            if ((t1v - t2v) < THETA || (t2v - t3v) < THETA) {
                int fi = atomicAdd(&g_nflag, 1);
                if (fi < MAXFLAG) g_flagrows[fi] = gr;
            }
        }
    }
}

// ---------------------------------------------------------------------------
// Refinement (unchanged): RB flagged rows per block, exact fp32 recompute
// ---------------------------------------------------------------------------
__global__ void __launch_bounds__(256) refine_kernel(
        const float* __restrict__ x, const float* __restrict__ W,
        const float* __restrict__ tptr, float* __restrict__ out, int M) {
    extern __shared__ float rsh[];
    float* sx = rsh;
    float* sp = rsh + RB * D_DIM;

    int nf = g_nflag;
    if (nf > MAXFLAG) nf = MAXFLAG;
    int base = blockIdx.x * RB;
    if (base >= nf) return;
    int nr = nf - base;
    if (nr > RB) nr = RB;

    int t = threadIdx.x;
    int rows[RB];
#pragma unroll
    for (int lr = 0; lr < RB; lr++) {
        int fi = base + (lr < nr ? lr : nr - 1);
        rows[lr] = g_flagrows[fi];
    }
    for (int lr = 0; lr < RB; lr++)
        for (int i = t; i < D_DIM; i += 256)
            sx[lr * D_DIM + i] = x[(size_t)rows[lr] * D_DIM + i];
    __syncthreads();

    float acc[RB];
#pragma unroll
    for (int lr = 0; lr < RB; lr++) acc[lr] = 0.0f;
#pragma unroll 4
    for (int k = 0; k < D_DIM; k++) {
        float wv = W[(size_t)k * EMB + t];
#pragma unroll
        for (int lr = 0; lr < RB; lr++)
            acc[lr] = fmaf(sx[lr * D_DIM + k], wv, acc[lr]);
    }
#pragma unroll
    for (int lr = 0; lr < RB; lr++) sp[lr * EMB + t] = acc[lr];
    __syncthreads();

    int w = t >> 5, lane = t & 31;
    if (w < nr) {
        int r = rows[w];
        const float* rp = sp + w * EMB;

        float ss = 0.0f;
#pragma unroll
        for (int i = 0; i < 8; i++) {
            float v = rp[i * 32 + lane];
            ss = fmaf(v, v, ss);
        }
#pragma unroll
        for (int off = 16; off > 0; off >>= 1)
            ss += __shfl_xor_sync(0xffffffffu, ss, off);
        float inv = 1.0f / sqrtf(ss + 1e-12f);

        float c0 = 0.0f, c1 = 0.0f;
#pragma unroll 8
        for (int k = 0; k < EMB; k++) {
            float pn = rp[k] * inv;
            c0 = fmaf(pn, g_embn[k * E_EXP + lane], c0);
            c1 = fmaf(pn, g_embn[k * E_EXP + lane + 32], c1);
        }

        float temp = tptr[0];
        float l0 = c0 * temp;
        float l1 = c1 * temp;

        float bv = l0; int bi = lane;
        if (l1 > bv) { bv = l1; bi = lane + 32; }
#pragma unroll
        for (int off = 16; off > 0; off >>= 1) {
            float ov = __shfl_xor_sync(0xffffffffu, bv, off);
            int   oi = __shfl_xor_sync(0xffffffffu, bi, off);
            if (ov > bv || (ov == bv && oi < bi)) { bv = ov; bi = oi; }
        }
        float t1v = bv; int t1i = bi;

        float m0 = (lane == t1i)      ? -INFINITY : l0;
        float m1 = (lane + 32 == t1i) ? -INFINITY : l1;
        bv = m0; bi = lane;
        if (m1 > bv || (m1 == bv && (lane + 32) < bi)) { bv = m1; bi = lane + 32; }
#pragma unroll
        for (int off = 16; off > 0; off >>= 1) {
            float ov = __shfl_xor_sync(0xffffffffu, bv, off);
            int   oi = __shfl_xor_sync(0xffffffffu, bi, off);
            if (ov > bv || (ov == bv && oi < bi)) { bv = ov; bi = oi; }
        }
        float t2v = bv; int t2i = bi;

        float ex0 = expf(l0 - t1v);
        float ex1 = expf(l1 - t1v);
        float tot = ex0 + ex1;
#pragma unroll
        for (int off = 16; off > 0; off >>= 1)
            tot += __shfl_xor_sync(0xffffffffu, tot, off);
        float r0 = ex0 / tot;
        float r1 = ex1 / tot;

        float eT = expf(t2v - t1v);
        float denom = 1.0f + eT;
        float w1 = 1.0f / denom;
        float w2 = eT / denom;
        float ew0 = (lane == t1i) ? w1 : ((lane == t2i) ? w2 : 0.0f);
        float ew1 = (lane + 32 == t1i) ? w1 : ((lane + 32 == t2i) ? w2 : 0.0f);

        size_t nM = (size_t)M;
        size_t ro = (size_t)r * 64;
        out[ro + lane]              = ew0;
        out[ro + lane + 32]         = ew1;
        out[nM * 66 + ro + lane]    = l0;
        out[nM * 66 + ro + lane + 32]  = l1;
        out[nM * 130 + ro + lane]   = c0;
        out[nM * 130 + ro + lane + 32] = c1;
        out[nM * 194 + ro + lane]   = r0;
        out[nM * 194 + ro + lane + 32] = r1;
        if (lane == 0) {
            out[nM * 64 + (size_t)r * 2]     = (float)t1i;
            out[nM * 64 + (size_t)r * 2 + 1] = (float)t2i;
        }
    }
}

// ---------------------------------------------------------------------------
extern "C" void kernel_launch(void* const* d_in, const int* in_sizes, int n_in,
                              void* d_out, int out_size) {
    const float* x    = (const float*)d_in[0];
    const float* W    = (const float*)d_in[1];
    const float* emb  = (const float*)d_in[2];
    const float* temp = (const float*)d_in[3];
    float* out = (float*)d_out;

    int M = in_sizes[0] / D_DIM;

    splitw_kernel<<<256, 256>>>(W);
    embn_kernel<<<E_EXP, EMB>>>(emb);

    int gsmem = NSTAGE * (int)STAGE_BYTES;   // 147456 B
    cudaFuncSetAttribute(mma_gemm_kernel,
                         cudaFuncAttributeMaxDynamicSharedMemorySize, gsmem);
    mma_gemm_kernel<<<M / 128, 512, gsmem>>>(x, M);

    cudaFuncSetAttribute(gate_kernel,
                         cudaFuncAttributeMaxDynamicSharedMemorySize, (int)GATE_SMEM);
    gate_kernel<<<M / 64, 256, GATE_SMEM>>>(temp, out, M);

    int rsmem = (RB * D_DIM + RB * EMB) * (int)sizeof(float);
    cudaFuncSetAttribute(refine_kernel,
                         cudaFuncAttributeMaxDynamicSharedMemorySize, rsmem);
    refine_kernel<<<(MAXFLAG + RB - 1) / RB, 256, rsmem>>>(x, W, temp, out, M);
}

// round 12
// speedup vs baseline: 1.0722x; 1.0722x over previous
#include <cuda_runtime.h>
#include <cuda_bf16.h>
#include <math.h>
#include <stdint.h>

#define D_DIM 2048
#define EMB   256
#define E_EXP 64
#define MAX_N 65536
#define THETA 2e-4f
#define MAXFLAG 8192
#define RB 8

// ---------------------------------------------------------------------------
// Device-global scratch
// ---------------------------------------------------------------------------
__device__ float g_proj[(size_t)MAX_N * EMB];
__device__ float g_embn[EMB * E_EXP];
__device__ int   g_nflag;
__device__ int   g_flagrows[MAXFLAG];

__device__ __align__(128) unsigned char g_whi[(size_t)EMB * D_DIM * 2];
__device__ __align__(128) unsigned char g_wlo[(size_t)EMB * D_DIM * 2];
__device__ __align__(128) unsigned char g_ebhi[32768];
__device__ __align__(128) unsigned char g_eblo[32768];

// ---------------------------------------------------------------------------
// Base-ISA PTX helpers
// ---------------------------------------------------------------------------
__device__ __forceinline__ uint32_t smem_u32(const void* p) {
    uint32_t a;
    asm("{ .reg .u64 t; cvta.to.shared.u64 t, %1; cvt.u32.u64 %0, t; }"
        : "=r"(a) : "l"(p));
    return a;
}
__device__ __forceinline__ void cp16(uint32_t s, const void* g) {
    asm volatile("cp.async.cg.shared.global [%0], [%1], 16;"
                 :: "r"(s), "l"(g) : "memory");
}
#define CP_COMMIT() asm volatile("cp.async.commit_group;" ::: "memory")
#define CP_WAIT(n)  asm volatile("cp.async.wait_group %0;" :: "n"(n) : "memory")

#define LDSM4(R, a)                                                            \
    asm volatile("ldmatrix.sync.aligned.m8n8.x4.shared.b16 {%0,%1,%2,%3}, [%4];" \
        : "=r"((R)[0]), "=r"((R)[1]), "=r"((R)[2]), "=r"((R)[3]) : "r"(a))

#define MMA16816(C, A, B0, B1)                                                 \
    asm volatile(                                                              \
        "mma.sync.aligned.m16n8k16.row.col.f32.bf16.bf16.f32 "                 \
        "{%0,%1,%2,%3}, {%4,%5,%6,%7}, {%8,%9}, {%0,%1,%2,%3};"                \
        : "+f"((C)[0]), "+f"((C)[1]), "+f"((C)[2]), "+f"((C)[3])               \
        : "r"((A)[0]), "r"((A)[1]), "r"((A)[2]), "r"((A)[3]),                  \
          "r"(B0), "r"(B1))

__device__ __forceinline__ uint32_t swz(int r, int c) {
    return (uint32_t)(r * 64 + ((c ^ ((r >> 1) & 3)) * 16));
}

// ---------------------------------------------------------------------------
// split + transpose W [2048,256] -> [256][2048] (hi, lo) bf16
// ---------------------------------------------------------------------------
__global__ void __launch_bounds__(256) splitw_kernel(const float* __restrict__ W) {
    int idx = blockIdx.x * 256 + threadIdx.x;
    int n = idx >> 8;
    int k = (idx & 255) << 3;

    union { __nv_bfloat16 h[8]; uint4 v; } ph, pl;
#pragma unroll
    for (int i = 0; i < 8; i++) {
        float f = W[(size_t)(k + i) * EMB + n];
        __nv_bfloat16 hi = __float2bfloat16(f);
        ph.h[i] = hi;
        pl.h[i] = __float2bfloat16(f - __bfloat162float(hi));
    }
    size_t off = (size_t)n * (D_DIM * 2) + (size_t)k * 2;
    *(uint4*)(g_whi + off) = ph.v;
    *(uint4*)(g_wlo + off) = pl.v;
}

// ---------------------------------------------------------------------------
// normalize expert_emb columns; emit expert-major split emb_n^T (swizzled)
// ---------------------------------------------------------------------------
__global__ void embn_kernel(const float* __restrict__ emb) {
    __shared__ float red[EMB];
    int e = blockIdx.x;
    int k = threadIdx.x;
    if (e == 0 && k == 0) g_nflag = 0;
    float v = emb[(size_t)k * E_EXP + e];
    red[k] = v * v;
    __syncthreads();
#pragma unroll
    for (int s = 128; s > 0; s >>= 1) {
        if (k < s) red[k] += red[k + s];
        __syncthreads();
    }
    float inv = 1.0f / sqrtf(red[0] + 1e-12f);
    float vn = v * inv;
    g_embn[(size_t)k * E_EXP + e] = vn;

    __nv_bfloat16 hi = __float2bfloat16(vn);
    __nv_bfloat16 lo = __float2bfloat16(vn - __bfloat162float(hi));
    uint32_t addr = (uint32_t)(k >> 5) * 4096 + swz(e, (k & 31) >> 3) + (k & 7) * 2;
    *(__nv_bfloat16*)(g_ebhi + addr) = hi;
    *(__nv_bfloat16*)(g_eblo + addr) = lo;
}

// ---------------------------------------------------------------------------
// GEMM v5: back to 256 threads / 2 CTAs/SM (the R7 scheduling win) with the
// fused in-kernel A split. 128x128 tile, 8 warps, warp tile 32x64, 3 stages.
// B frags in 32-col halves keep live regs ~122 < 128 (no spills).
// ---------------------------------------------------------------------------
#define NSTAGE      3
#define STAGE_BYTES 32768u   // Ahi 8K | Alo 8K | Bhi 8K | Blo 8K
#define OFF_ALO     8192u
#define OFF_BHI     16384u
#define OFF_BLO     24576u
#define NKT         (D_DIM / 32)   // 64

__global__ void __launch_bounds__(256, 2) mma_gemm_kernel(
        const float* __restrict__ x, int M) {
    extern __shared__ __align__(128) unsigned char smem[];
    uint32_t sb = smem_u32(smem);
    int tid  = threadIdx.x;
    int lane = tid & 31;
    int w    = tid >> 5;     // 0..7
    int mw   = w & 3;        // M slice (32 rows)
    int nw   = w >> 2;       // N slice (64 cols)

    size_t bm = (size_t)blockIdx.y * 128;
    int    bn = blockIdx.x * 128;

    // loaders: thread t -> row t/2 (0..127), chunks (t&1)*2 + {0,1}
    int alr  = tid >> 1;
    int alq2 = (tid & 1) * 2;
    const float* xrow = x + (bm + alr) * D_DIM + alq2 * 8;
    size_t brow = (size_t)(bn + alr) * (D_DIM * 2) + (size_t)alq2 * 16;

    float f[16];   // two 16B chunks of fp32 A (dead during MMA issue region)
    auto ldga = [&](int kt) {
        const float4* p = (const float4*)(xrow + (size_t)kt * 32);
#pragma unroll
        for (int q = 0; q < 4; q++) {
            float4 v = p[q];
            f[q * 4 + 0] = v.x; f[q * 4 + 1] = v.y;
            f[q * 4 + 2] = v.z; f[q * 4 + 3] = v.w;
        }
    };
    auto stsa = [&](int s) {
#pragma unroll
        for (int c2 = 0; c2 < 2; c2++) {
            union { __nv_bfloat16 h[8]; uint4 v; } ph, pl;
#pragma unroll
            for (int i = 0; i < 8; i++) {
                float fv = f[c2 * 8 + i];
                __nv_bfloat16 hi = __float2bfloat16(fv);
                ph.h[i] = hi;
                pl.h[i] = __float2bfloat16(fv - __bfloat162float(hi));
            }
            uint32_t so = (uint32_t)s * STAGE_BYTES + swz(alr, alq2 + c2);
            *(uint4*)(smem + so) = ph.v;
            *(uint4*)(smem + so + OFF_ALO) = pl.v;
        }
    };
    auto cpb = [&](int kt, int s) {
        uint32_t st = sb + (uint32_t)s * STAGE_BYTES;
        size_t go = brow + (size_t)kt * 64;
        uint32_t so0 = swz(alr, alq2);
        uint32_t so1 = swz(alr, alq2 + 1);
        cp16(st + OFF_BHI + so0, g_whi + go);
        cp16(st + OFF_BHI + so1, g_whi + go + 16);
        cp16(st + OFF_BLO + so0, g_wlo + go);
        cp16(st + OFF_BLO + so1, g_wlo + go + 16);
        CP_COMMIT();
    };

    // prologue: stages 0, 1
    ldga(0); stsa(0); cpb(0, 0);
    ldga(1); stsa(1); cpb(1, 1);

    float acc[2][8][4];
#pragma unroll
    for (int i = 0; i < 2; i++)
#pragma unroll
        for (int j = 0; j < 8; j++)
#pragma unroll
            for (int q = 0; q < 4; q++) acc[i][j][q] = 0.0f;

    int a_r  = lane & 15;
    int a_cb = lane >> 4;
    int b_r  = (lane & 7) + ((lane >> 4) & 1) * 8;
    int b_cb = (lane >> 3) & 1;

    for (int kt = 0; kt < NKT; kt++) {
        CP_WAIT(1);
        __syncthreads();

        int nx = kt + 2;
        bool pf = nx < NKT;
        if (pf) { ldga(nx); cpb(nx, nx % NSTAGE); }
        else    { CP_COMMIT(); }   // keep wait_group accounting exact

        uint32_t st = sb + (uint32_t)(kt % NSTAGE) * STAGE_BYTES;

#pragma unroll
        for (int kh = 0; kh < 2; kh++) {
            uint32_t ahi[2][4], alo[2][4];
#pragma unroll
            for (int i = 0; i < 2; i++) {
                int r = mw * 32 + i * 16 + a_r;
                uint32_t ad = st + swz(r, 2 * kh + a_cb);
                LDSM4(ahi[i], ad);
                LDSM4(alo[i], ad + OFF_ALO);
            }
#pragma unroll
            for (int h = 0; h < 2; h++) {   // 32-col B halves (reg pressure)
                uint32_t bhi[2][4], blo[2][4];
#pragma unroll
                for (int j2 = 0; j2 < 2; j2++) {
                    int r = nw * 64 + h * 32 + j2 * 16 + b_r;
                    uint32_t ad = st + OFF_BHI + swz(r, 2 * kh + b_cb);
                    LDSM4(bhi[j2], ad);
                    LDSM4(blo[j2], ad + (OFF_BLO - OFF_BHI));
                }
#pragma unroll
                for (int i = 0; i < 2; i++) {
#pragma unroll
                    for (int j = 0; j < 4; j++) {
                        uint32_t* bh = &bhi[j >> 1][(j & 1) * 2];
                        uint32_t* bl = &blo[j >> 1][(j & 1) * 2];
                        MMA16816(acc[i][h * 4 + j], ahi[i], bh[0], bh[1]);
                        MMA16816(acc[i][h * 4 + j], ahi[i], bl[0], bl[1]);
                        MMA16816(acc[i][h * 4 + j], alo[i], bh[0], bh[1]);
                    }
                }
            }
        }
        if (pf) stsa(nx % NSTAGE);   // stage (kt-1)%3: reads done (top sync)
    }

#pragma unroll
    for (int i = 0; i < 2; i++) {
#pragma unroll
        for (int j = 0; j < 8; j++) {
            size_t r0 = bm + mw * 32 + i * 16 + (lane >> 2);
            int col = bn + nw * 64 + j * 8 + 2 * (lane & 3);
            *(float2*)&g_proj[r0 * EMB + col] =
                make_float2(acc[i][j][0], acc[i][j][1]);
            *(float2*)&g_proj[(r0 + 8) * EMB + col] =
                make_float2(acc[i][j][2], acc[i][j][3]);
        }
    }
}

// ---------------------------------------------------------------------------
// Gate kernel v2 (unchanged): tensor-core cos, one CTA = 64 rows
// ---------------------------------------------------------------------------
#define SM_BHI  0u
#define SM_BLO  32768u
#define SM_AHI  65536u
#define SM_ALO  98304u
#define SM_SCOS 131072u            // float[64][66]
#define SM_SSUM 147968u            // float[64]
#define GATE_SMEM 148224u

__global__ void __launch_bounds__(256) gate_kernel(
        const float* __restrict__ tptr, float* __restrict__ out, int M) {
    extern __shared__ __align__(128) unsigned char smem[];
    uint32_t sb = smem_u32(smem);
    float* scos = (float*)(smem + SM_SCOS);
    float* ssum = (float*)(smem + SM_SSUM);

    int t = threadIdx.x;
    int lane = t & 31;
    int w = t >> 5;

    {
        const uint4* shi = (const uint4*)g_ebhi;
        const uint4* slo = (const uint4*)g_eblo;
        uint4* dhi = (uint4*)(smem + SM_BHI);
        uint4* dlo = (uint4*)(smem + SM_BLO);
#pragma unroll
        for (int i = 0; i < 8; i++) {
            dhi[t + i * 256] = shi[t + i * 256];
            dlo[t + i * 256] = slo[t + i * 256];
        }
    }

    int gr0 = blockIdx.x * 64;
    int lr = t >> 2;
    int q  = t & 3;

    float4 f[16];
    const float4* xp = (const float4*)(g_proj + (size_t)(gr0 + lr) * EMB + q * 64);
    float ss = 0.0f;
#pragma unroll
    for (int i = 0; i < 16; i++) {
        float4 v = xp[i];
        f[i] = v;
        ss += v.x * v.x + v.y * v.y + v.z * v.z + v.w * v.w;
    }
    ss += __shfl_xor_sync(0xffffffffu, ss, 1);
    ss += __shfl_xor_sync(0xffffffffu, ss, 2);
    if (q == 0) ssum[lr] = ss;

#pragma unroll
    for (int j = 0; j < 8; j++) {
        float fv[8] = {f[2*j].x, f[2*j].y, f[2*j].z, f[2*j].w,
                       f[2*j+1].x, f[2*j+1].y, f[2*j+1].z, f[2*j+1].w};
        union { __nv_bfloat16 h[8]; uint4 v; } ph, pl;
#pragma unroll
        for (int i = 0; i < 8; i++) {
            __nv_bfloat16 hi = __float2bfloat16(fv[i]);
            ph.h[i] = hi;
            pl.h[i] = __float2bfloat16(fv[i] - __bfloat162float(hi));
        }
        uint32_t so = (uint32_t)(q * 2 + (j >> 2)) * 4096 + swz(lr, j & 3);
        *(uint4*)(smem + SM_AHI + so) = ph.v;
        *(uint4*)(smem + SM_ALO + so) = pl.v;
    }
    __syncthreads();

    int mw = w & 3;
    int nw = w >> 2;
    float acc[4][4];
#pragma unroll
    for (int j = 0; j < 4; j++)
#pragma unroll
        for (int qq = 0; qq < 4; qq++) acc[j][qq] = 0.0f;

    int a_r = lane & 15;
    int a_cb = lane >> 4;
    int b_r = (lane & 7) + ((lane >> 4) & 1) * 8;
    int b_cb = (lane >> 3) & 1;

#pragma unroll
    for (int kc = 0; kc < 8; kc++) {
#pragma unroll
        for (int kh = 0; kh < 2; kh++) {
            uint32_t ahi[4], alo[4], bhi[2][4], blo[2][4];
            uint32_t ca = SM_AHI + (uint32_t)kc * 4096 + swz(mw * 16 + a_r, 2 * kh + a_cb);
            LDSM4(ahi, sb + ca);
            LDSM4(alo, sb + ca + (SM_ALO - SM_AHI));
#pragma unroll
            for (int j2 = 0; j2 < 2; j2++) {
                uint32_t cb = SM_BHI + (uint32_t)kc * 4096
                            + swz(nw * 32 + j2 * 16 + b_r, 2 * kh + b_cb);
                LDSM4(bhi[j2], sb + cb);
                LDSM4(blo[j2], sb + cb + (SM_BLO - SM_BHI));
            }
#pragma unroll
            for (int j = 0; j < 4; j++) {
                uint32_t* bh = &bhi[j >> 1][(j & 1) * 2];
                uint32_t* bl = &blo[j >> 1][(j & 1) * 2];
                MMA16816(acc[j], ahi, bh[0], bh[1]);
                MMA16816(acc[j], ahi, bl[0], bl[1]);
                MMA16816(acc[j], alo, bh[0], bh[1]);
            }
        }
    }

    int r0 = mw * 16 + (lane >> 2);
    float inv0 = 1.0f / sqrtf(ssum[r0] + 1e-12f);
    float inv1 = 1.0f / sqrtf(ssum[r0 + 8] + 1e-12f);
#pragma unroll
    for (int j = 0; j < 4; j++) {
        int col = nw * 32 + j * 8 + (lane & 3) * 2;
        scos[r0 * 66 + col]       = acc[j][0] * inv0;
        scos[r0 * 66 + col + 1]   = acc[j][1] * inv0;
        scos[(r0 + 8) * 66 + col]     = acc[j][2] * inv1;
        scos[(r0 + 8) * 66 + col + 1] = acc[j][3] * inv1;
    }
    __syncthreads();

    float temp = tptr[0];
    size_t nM = (size_t)M;
    float* out_ew  = out;
    float* out_ti  = out + nM * 64;
    float* out_lg  = out + nM * 66;
    float* out_cs  = out + nM * 130;
    float* out_raw = out + nM * 194;

#pragma unroll
    for (int r8 = 0; r8 < 8; r8++) {
        int row = w * 8 + r8;
        int gr = gr0 + row;
        float c0 = scos[row * 66 + lane];
        float c1 = scos[row * 66 + lane + 32];
        float l0 = c0 * temp;
        float l1 = c1 * temp;

        float bv = l0; int bi = lane;
        if (l1 > bv) { bv = l1; bi = lane + 32; }
#pragma unroll
        for (int off = 16; off > 0; off >>= 1) {
            float ov = __shfl_xor_sync(0xffffffffu, bv, off);
            int   oi = __shfl_xor_sync(0xffffffffu, bi, off);
            if (ov > bv || (ov == bv && oi < bi)) { bv = ov; bi = oi; }
        }
        float t1v = bv; int t1i = bi;

        float m0 = (lane == t1i)      ? -INFINITY : l0;
        float m1 = (lane + 32 == t1i) ? -INFINITY : l1;
        bv = m0; bi = lane;
        if (m1 > bv || (m1 == bv && (lane + 32) < bi)) { bv = m1; bi = lane + 32; }
#pragma unroll
        for (int off = 16; off > 0; off >>= 1) {
            float ov = __shfl_xor_sync(0xffffffffu, bv, off);
            int   oi = __shfl_xor_sync(0xffffffffu, bi, off);
            if (ov > bv || (ov == bv && oi < bi)) { bv = ov; bi = oi; }
        }
        float t2v = bv; int t2i = bi;

        float p0 = (lane == t1i || lane == t2i) ? -INFINITY : l0;
        float p1 = (lane + 32 == t1i || lane + 32 == t2i) ? -INFINITY : l1;
        float t3v = fmaxf(p0, p1);
#pragma unroll
        for (int off = 16; off > 0; off >>= 1)
            t3v = fmaxf(t3v, __shfl_xor_sync(0xffffffffu, t3v, off));

        float ex0 = expf(l0 - t1v);
        float ex1 = expf(l1 - t1v);
        float tot = ex0 + ex1;
#pragma unroll
        for (int off = 16; off > 0; off >>= 1)
            tot += __shfl_xor_sync(0xffffffffu, tot, off);
        float r0s = ex0 / tot;
        float r1s = ex1 / tot;

        float eT = expf(t2v - t1v);
        float denom = 1.0f + eT;
        float w1 = 1.0f / denom;
        float w2 = eT / denom;
        float ew0 = (lane == t1i) ? w1 : ((lane == t2i) ? w2 : 0.0f);
        float ew1 = (lane + 32 == t1i) ? w1 : ((lane + 32 == t2i) ? w2 : 0.0f);

        size_t ro = (size_t)gr * 64;
        out_ew[ro + lane]       = ew0;
        out_ew[ro + lane + 32]  = ew1;
        out_lg[ro + lane]       = l0;
        out_lg[ro + lane + 32]  = l1;
        out_cs[ro + lane]       = c0;
        out_cs[ro + lane + 32]  = c1;
        out_raw[ro + lane]      = r0s;
        out_raw[ro + lane + 32] = r1s;
        if (lane == 0) {
            out_ti[(size_t)gr * 2]     = (float)t1i;
            out_ti[(size_t)gr * 2 + 1] = (float)t2i;
            if ((t1v - t2v) < THETA || (t2v - t3v) < THETA) {
                int fi = atomicAdd(&g_nflag, 1);
                if (fi < MAXFLAG) g_flagrows[fi] = gr;
            }
        }
    }
}

// ---------------------------------------------------------------------------
// Refinement (unchanged): RB flagged rows per block, exact fp32 recompute
// ---------------------------------------------------------------------------
__global__ void __launch_bounds__(256) refine_kernel(
        const float* __restrict__ x, const float* __restrict__ W,
        const float* __restrict__ tptr, float* __restrict__ out, int M) {
    extern __shared__ float rsh[];
    float* sx = rsh;
    float* sp = rsh + RB * D_DIM;

    int nf = g_nflag;
    if (nf > MAXFLAG) nf = MAXFLAG;
    int base = blockIdx.x * RB;
    if (base >= nf) return;
    int nr = nf - base;
    if (nr > RB) nr = RB;

    int t = threadIdx.x;
    int rows[RB];
#pragma unroll
    for (int lr = 0; lr < RB; lr++) {
        int fi = base + (lr < nr ? lr : nr - 1);
        rows[lr] = g_flagrows[fi];
    }
    for (int lr = 0; lr < RB; lr++)
        for (int i = t; i < D_DIM; i += 256)
            sx[lr * D_DIM + i] = x[(size_t)rows[lr] * D_DIM + i];
    __syncthreads();

    float acc[RB];
#pragma unroll
    for (int lr = 0; lr < RB; lr++) acc[lr] = 0.0f;
#pragma unroll 4
    for (int k = 0; k < D_DIM; k++) {
        float wv = W[(size_t)k * EMB + t];
#pragma unroll
        for (int lr = 0; lr < RB; lr++)
            acc[lr] = fmaf(sx[lr * D_DIM + k], wv, acc[lr]);
    }
#pragma unroll
    for (int lr = 0; lr < RB; lr++) sp[lr * EMB + t] = acc[lr];
    __syncthreads();

    int w = t >> 5, lane = t & 31;
    if (w < nr) {
        int r = rows[w];
        const float* rp = sp + w * EMB;

        float ss = 0.0f;
#pragma unroll
        for (int i = 0; i < 8; i++) {
            float v = rp[i * 32 + lane];
            ss = fmaf(v, v, ss);
        }
#pragma unroll
        for (int off = 16; off > 0; off >>= 1)
            ss += __shfl_xor_sync(0xffffffffu, ss, off);
        float inv = 1.0f / sqrtf(ss + 1e-12f);

        float c0 = 0.0f, c1 = 0.0f;
#pragma unroll 8
        for (int k = 0; k < EMB; k++) {
            float pn = rp[k] * inv;
            c0 = fmaf(pn, g_embn[k * E_EXP + lane], c0);
            c1 = fmaf(pn, g_embn[k * E_EXP + lane + 32], c1);
        }

        float temp = tptr[0];
        float l0 = c0 * temp;
        float l1 = c1 * temp;

        float bv = l0; int bi = lane;
        if (l1 > bv) { bv = l1; bi = lane + 32; }
#pragma unroll
        for (int off = 16; off > 0; off >>= 1) {
            float ov = __shfl_xor_sync(0xffffffffu, bv, off);
            int   oi = __shfl_xor_sync(0xffffffffu, bi, off);
            if (ov > bv || (ov == bv && oi < bi)) { bv = ov; bi = oi; }
        }
        float t1v = bv; int t1i = bi;

        float m0 = (lane == t1i)      ? -INFINITY : l0;
        float m1 = (lane + 32 == t1i) ? -INFINITY : l1;
        bv = m0; bi = lane;
        if (m1 > bv || (m1 == bv && (lane + 32) < bi)) { bv = m1; bi = lane + 32; }
#pragma unroll
        for (int off = 16; off > 0; off >>= 1) {
            float ov = __shfl_xor_sync(0xffffffffu, bv, off);
            int   oi = __shfl_xor_sync(0xffffffffu, bi, off);
            if (ov > bv || (ov == bv && oi < bi)) { bv = ov; bi = oi; }
        }
        float t2v = bv; int t2i = bi;

        float ex0 = expf(l0 - t1v);
        float ex1 = expf(l1 - t1v);
        float tot = ex0 + ex1;
#pragma unroll
        for (int off = 16; off > 0; off >>= 1)
            tot += __shfl_xor_sync(0xffffffffu, tot, off);
        float r0 = ex0 / tot;
        float r1 = ex1 / tot;

        float eT = expf(t2v - t1v);
        float denom = 1.0f + eT;
        float w1 = 1.0f / denom;
        float w2 = eT / denom;
        float ew0 = (lane == t1i) ? w1 : ((lane == t2i) ? w2 : 0.0f);
        float ew1 = (lane + 32 == t1i) ? w1 : ((lane + 32 == t2i) ? w2 : 0.0f);

        size_t nM = (size_t)M;
        size_t ro = (size_t)r * 64;
        out[ro + lane]              = ew0;
        out[ro + lane + 32]         = ew1;
        out[nM * 66 + ro + lane]    = l0;
        out[nM * 66 + ro + lane + 32]  = l1;
        out[nM * 130 + ro + lane]   = c0;
        out[nM * 130 + ro + lane + 32] = c1;
        out[nM * 194 + ro + lane]   = r0;
        out[nM * 194 + ro + lane + 32] = r1;
        if (lane == 0) {
            out[nM * 64 + (size_t)r * 2]     = (float)t1i;
            out[nM * 64 + (size_t)r * 2 + 1] = (float)t2i;
        }
    }
}

// ---------------------------------------------------------------------------
extern "C" void kernel_launch(void* const* d_in, const int* in_sizes, int n_in,
                              void* d_out, int out_size) {
    const float* x    = (const float*)d_in[0];
    const float* W    = (const float*)d_in[1];
    const float* emb  = (const float*)d_in[2];
    const float* temp = (const float*)d_in[3];
    float* out = (float*)d_out;

    int M = in_sizes[0] / D_DIM;

    splitw_kernel<<<256, 256>>>(W);
    embn_kernel<<<E_EXP, EMB>>>(emb);

    int gsmem = NSTAGE * (int)STAGE_BYTES;   // 98304 B
    cudaFuncSetAttribute(mma_gemm_kernel,
                         cudaFuncAttributeMaxDynamicSharedMemorySize, gsmem);
    dim3 grid(EMB / 128, M / 128);           // N-fastest: x reused in L2
    mma_gemm_kernel<<<grid, 256, gsmem>>>(x, M);

    cudaFuncSetAttribute(gate_kernel,
                         cudaFuncAttributeMaxDynamicSharedMemorySize, (int)GATE_SMEM);
    gate_kernel<<<M / 64, 256, GATE_SMEM>>>(temp, out, M);

    int rsmem = (RB * D_DIM + RB * EMB) * (int)sizeof(float);
    cudaFuncSetAttribute(refine_kernel,
                         cudaFuncAttributeMaxDynamicSharedMemorySize, rsmem);
    refine_kernel<<<(MAXFLAG + RB - 1) / RB, 256, rsmem>>>(x, W, temp, out, M);
}

// round 13
// speedup vs baseline: 1.2846x; 1.1981x over previous
#include <cuda_runtime.h>
#include <cuda_bf16.h>
#include <cuda_fp16.h>
#include <math.h>
#include <stdint.h>

#define D_DIM 2048
#define EMB   256
#define E_EXP 64
#define MAX_N 65536
#define THETA 2e-4f
#define MAXFLAG 8192
#define RB 8

// ---------------------------------------------------------------------------
// Device-global scratch
// ---------------------------------------------------------------------------
__device__ float g_proj[(size_t)MAX_N * EMB];
__device__ float g_embn[EMB * E_EXP];
__device__ int   g_nflag;
__device__ int   g_flagrows[MAXFLAG];

// W^T split (fp16): [256][2048] hi, lo
__device__ __align__(128) unsigned char g_whi[(size_t)EMB * D_DIM * 2];
__device__ __align__(128) unsigned char g_wlo[(size_t)EMB * D_DIM * 2];
// expert-major split emb_n^T (fp16), pre-swizzled ldmatrix layout
__device__ __align__(128) unsigned char g_ebhi[32768];
__device__ __align__(128) unsigned char g_eblo[32768];

// ---------------------------------------------------------------------------
// Base-ISA PTX helpers
// ---------------------------------------------------------------------------
__device__ __forceinline__ uint32_t smem_u32(const void* p) {
    uint32_t a;
    asm("{ .reg .u64 t; cvta.to.shared.u64 t, %1; cvt.u32.u64 %0, t; }"
        : "=r"(a) : "l"(p));
    return a;
}
__device__ __forceinline__ void cp16(uint32_t s, const void* g) {
    asm volatile("cp.async.cg.shared.global [%0], [%1], 16;"
                 :: "r"(s), "l"(g) : "memory");
}
#define CP_COMMIT() asm volatile("cp.async.commit_group;" ::: "memory")
#define CP_WAIT(n)  asm volatile("cp.async.wait_group %0;" :: "n"(n) : "memory")

#define LDSM4(R, a)                                                            \
    asm volatile("ldmatrix.sync.aligned.m8n8.x4.shared.b16 {%0,%1,%2,%3}, [%4];" \
        : "=r"((R)[0]), "=r"((R)[1]), "=r"((R)[2]), "=r"((R)[3]) : "r"(a))

// fp16 tensor-core MMA, fp32 accumulate
#define MMA16816H(C, A, B0, B1)                                                \
    asm volatile(                                                              \
        "mma.sync.aligned.m16n8k16.row.col.f32.f16.f16.f32 "                   \
        "{%0,%1,%2,%3}, {%4,%5,%6,%7}, {%8,%9}, {%0,%1,%2,%3};"                \
        : "+f"((C)[0]), "+f"((C)[1]), "+f"((C)[2]), "+f"((C)[3])               \
        : "r"((A)[0]), "r"((A)[1]), "r"((A)[2]), "r"((A)[3]),                  \
          "r"(B0), "r"(B1))

__device__ __forceinline__ uint32_t swz(int r, int c) {
    return (uint32_t)(r * 64 + ((c ^ ((r >> 1) & 3)) * 16));
}

// ---------------------------------------------------------------------------
// split + transpose W [2048,256] -> [256][2048] (hi, lo) fp16
// ---------------------------------------------------------------------------
__global__ void __launch_bounds__(256) splitw_kernel(const float* __restrict__ W) {
    int idx = blockIdx.x * 256 + threadIdx.x;
    int n = idx >> 8;
    int k = (idx & 255) << 3;

    union { __half h[8]; uint4 v; } ph, pl;
#pragma unroll
    for (int i = 0; i < 8; i++) {
        float f = W[(size_t)(k + i) * EMB + n];
        __half hi = __float2half_rn(f);
        ph.h[i] = hi;
        pl.h[i] = __float2half_rn(f - __half2float(hi));
    }
    size_t off = (size_t)n * (D_DIM * 2) + (size_t)k * 2;
    *(uint4*)(g_whi + off) = ph.v;
    *(uint4*)(g_wlo + off) = pl.v;
}

// ---------------------------------------------------------------------------
// normalize expert_emb columns; emit expert-major split-fp16 emb_n^T
// ---------------------------------------------------------------------------
__global__ void embn_kernel(const float* __restrict__ emb) {
    __shared__ float red[EMB];
    int e = blockIdx.x;
    int k = threadIdx.x;
    if (e == 0 && k == 0) g_nflag = 0;
    float v = emb[(size_t)k * E_EXP + e];
    red[k] = v * v;
    __syncthreads();
#pragma unroll
    for (int s = 128; s > 0; s >>= 1) {
        if (k < s) red[k] += red[k + s];
        __syncthreads();
    }
    float inv = 1.0f / sqrtf(red[0] + 1e-12f);
    float vn = v * inv;
    g_embn[(size_t)k * E_EXP + e] = vn;

    __half hi = __float2half_rn(vn);
    __half lo = __float2half_rn(vn - __half2float(hi));
    uint32_t addr = (uint32_t)(k >> 5) * 4096 + swz(e, (k & 31) >> 3) + (k & 7) * 2;
    *(__half*)(g_ebhi + addr) = hi;
    *(__half*)(g_eblo + addr) = lo;
}

// ---------------------------------------------------------------------------
// GEMM v6: fp16 2-product (x_hi * (W_hi + W_lo)). 256 thr / 2 CTAs/SM,
// 128x128 tile, 8 warps, warp tile 32x64, 3 stages of 24KB, fused A split.
// ---------------------------------------------------------------------------
#define NSTAGE      3
#define STAGE_BYTES 24576u   // Ahi 8K | Bhi 8K | Blo 8K
#define OFF_BHI     8192u
#define OFF_BLO     16384u
#define NKT         (D_DIM / 32)   // 64

__global__ void __launch_bounds__(256, 2) mma_gemm_kernel(
        const float* __restrict__ x, int M) {
    extern __shared__ __align__(128) unsigned char smem[];
    uint32_t sb = smem_u32(smem);
    int tid  = threadIdx.x;
    int lane = tid & 31;
    int w    = tid >> 5;     // 0..7
    int mw   = w & 3;        // M slice (32 rows)
    int nw   = w >> 2;       // N slice (64 cols)

    size_t bm = (size_t)blockIdx.y * 128;
    int    bn = blockIdx.x * 128;

    // loaders: thread t -> row t/2 (0..127), chunks (t&1)*2 + {0,1}
    int alr  = tid >> 1;
    int alq2 = (tid & 1) * 2;
    const float* xrow = x + (bm + alr) * D_DIM + alq2 * 8;
    size_t brow = (size_t)(bn + alr) * (D_DIM * 2) + (size_t)alq2 * 16;

    float f[16];
    auto ldga = [&](int kt) {
        const float4* p = (const float4*)(xrow + (size_t)kt * 32);
#pragma unroll
        for (int q = 0; q < 4; q++) {
            float4 v = p[q];
            f[q * 4 + 0] = v.x; f[q * 4 + 1] = v.y;
            f[q * 4 + 2] = v.z; f[q * 4 + 3] = v.w;
        }
    };
    auto stsa = [&](int s) {
#pragma unroll
        for (int c2 = 0; c2 < 2; c2++) {
            union { __half h[8]; uint4 v; } ph;
#pragma unroll
            for (int i = 0; i < 8; i++)
                ph.h[i] = __float2half_rn(f[c2 * 8 + i]);
            uint32_t so = (uint32_t)s * STAGE_BYTES + swz(alr, alq2 + c2);
            *(uint4*)(smem + so) = ph.v;
        }
    };
    auto cpb = [&](int kt, int s) {
        uint32_t st = sb + (uint32_t)s * STAGE_BYTES;
        size_t go = brow + (size_t)kt * 64;
        uint32_t so0 = swz(alr, alq2);
        uint32_t so1 = swz(alr, alq2 + 1);
        cp16(st + OFF_BHI + so0, g_whi + go);
        cp16(st + OFF_BHI + so1, g_whi + go + 16);
        cp16(st + OFF_BLO + so0, g_wlo + go);
        cp16(st + OFF_BLO + so1, g_wlo + go + 16);
        CP_COMMIT();
    };

    // prologue: stages 0, 1
    ldga(0); stsa(0); cpb(0, 0);
    ldga(1); stsa(1); cpb(1, 1);

    float acc[2][8][4];
#pragma unroll
    for (int i = 0; i < 2; i++)
#pragma unroll
        for (int j = 0; j < 8; j++)
#pragma unroll
            for (int q = 0; q < 4; q++) acc[i][j][q] = 0.0f;

    int a_r  = lane & 15;
    int a_cb = lane >> 4;
    int b_r  = (lane & 7) + ((lane >> 4) & 1) * 8;
    int b_cb = (lane >> 3) & 1;

    for (int kt = 0; kt < NKT; kt++) {
        CP_WAIT(1);
        __syncthreads();

        int nx = kt + 2;
        bool pf = nx < NKT;
        if (pf) { ldga(nx); cpb(nx, nx % NSTAGE); }
        else    { CP_COMMIT(); }   // keep wait_group accounting exact

        uint32_t st = sb + (uint32_t)(kt % NSTAGE) * STAGE_BYTES;

#pragma unroll
        for (int kh = 0; kh < 2; kh++) {
            uint32_t ahi[2][4];
#pragma unroll
            for (int i = 0; i < 2; i++) {
                int r = mw * 32 + i * 16 + a_r;
                LDSM4(ahi[i], st + swz(r, 2 * kh + a_cb));
            }
#pragma unroll
            for (int h = 0; h < 2; h++) {   // 32-col B halves
                uint32_t bhi[2][4], blo[2][4];
#pragma unroll
                for (int j2 = 0; j2 < 2; j2++) {
                    int r = nw * 64 + h * 32 + j2 * 16 + b_r;
                    uint32_t ad = st + OFF_BHI + swz(r, 2 * kh + b_cb);
                    LDSM4(bhi[j2], ad);
                    LDSM4(blo[j2], ad + (OFF_BLO - OFF_BHI));
                }
#pragma unroll
                for (int i = 0; i < 2; i++) {
#pragma unroll
                    for (int j = 0; j < 4; j++) {
                        uint32_t* bh = &bhi[j >> 1][(j & 1) * 2];
                        uint32_t* bl = &blo[j >> 1][(j & 1) * 2];
                        MMA16816H(acc[i][h * 4 + j], ahi[i], bh[0], bh[1]);
                        MMA16816H(acc[i][h * 4 + j], ahi[i], bl[0], bl[1]);
                    }
                }
            }
        }
        if (pf) stsa(nx % NSTAGE);   // stage (kt-1)%3: reads done (top sync)
    }

#pragma unroll
    for (int i = 0; i < 2; i++) {
#pragma unroll
        for (int j = 0; j < 8; j++) {
            size_t r0 = bm + mw * 32 + i * 16 + (lane >> 2);
            int col = bn + nw * 64 + j * 8 + 2 * (lane & 3);
            *(float2*)&g_proj[r0 * EMB + col] =
                make_float2(acc[i][j][0], acc[i][j][1]);
            *(float2*)&g_proj[(r0 + 8) * EMB + col] =
                make_float2(acc[i][j][2], acc[i][j][3]);
        }
    }
}

// ---------------------------------------------------------------------------
// Gate kernel v3: fp16 2-product cos GEMM. One CTA = 64 rows.
// ---------------------------------------------------------------------------
#define SM_BHI  0u
#define SM_BLO  32768u
#define SM_AHI  65536u
#define SM_SCOS 98304u             // float[64][66]
#define SM_SSUM 115200u            // float[64]
#define GATE_SMEM 115456u

__global__ void __launch_bounds__(256) gate_kernel(
        const float* __restrict__ tptr, float* __restrict__ out, int M) {
    extern __shared__ __align__(128) unsigned char smem[];
    uint32_t sb = smem_u32(smem);
    float* scos = (float*)(smem + SM_SCOS);
    float* ssum = (float*)(smem + SM_SSUM);

    int t = threadIdx.x;
    int lane = t & 31;
    int w = t >> 5;

    {
        const uint4* shi = (const uint4*)g_ebhi;
        const uint4* slo = (const uint4*)g_eblo;
        uint4* dhi = (uint4*)(smem + SM_BHI);
        uint4* dlo = (uint4*)(smem + SM_BLO);
#pragma unroll
        for (int i = 0; i < 8; i++) {
            dhi[t + i * 256] = shi[t + i * 256];
            dlo[t + i * 256] = slo[t + i * 256];
        }
    }

    int gr0 = blockIdx.x * 64;
    int lr = t >> 2;
    int q  = t & 3;

    float4 f[16];
    const float4* xp = (const float4*)(g_proj + (size_t)(gr0 + lr) * EMB + q * 64);
    float ss = 0.0f;
#pragma unroll
    for (int i = 0; i < 16; i++) {
        float4 v = xp[i];
        f[i] = v;
        ss += v.x * v.x + v.y * v.y + v.z * v.z + v.w * v.w;
    }
    ss += __shfl_xor_sync(0xffffffffu, ss, 1);
    ss += __shfl_xor_sync(0xffffffffu, ss, 2);
    if (q == 0) ssum[lr] = ss;

#pragma unroll
    for (int j = 0; j < 8; j++) {
        float fv[8] = {f[2*j].x, f[2*j].y, f[2*j].z, f[2*j].w,
                       f[2*j+1].x, f[2*j+1].y, f[2*j+1].z, f[2*j+1].w};
        union { __half h[8]; uint4 v; } ph;
#pragma unroll
        for (int i = 0; i < 8; i++)
            ph.h[i] = __float2half_rn(fv[i]);
        uint32_t so = (uint32_t)(q * 2 + (j >> 2)) * 4096 + swz(lr, j & 3);
        *(uint4*)(smem + SM_AHI + so) = ph.v;
    }
    __syncthreads();

    int mw = w & 3;
    int nw = w >> 2;
    float acc[4][4];
#pragma unroll
    for (int j = 0; j < 4; j++)
#pragma unroll
        for (int qq = 0; qq < 4; qq++) acc[j][qq] = 0.0f;

    int a_r = lane & 15;
    int a_cb = lane >> 4;
    int b_r = (lane & 7) + ((lane >> 4) & 1) * 8;
    int b_cb = (lane >> 3) & 1;

#pragma unroll
    for (int kc = 0; kc < 8; kc++) {
#pragma unroll
        for (int kh = 0; kh < 2; kh++) {
            uint32_t ahi[4], bhi[2][4], blo[2][4];
            uint32_t ca = SM_AHI + (uint32_t)kc * 4096 + swz(mw * 16 + a_r, 2 * kh + a_cb);
            LDSM4(ahi, sb + ca);
#pragma unroll
            for (int j2 = 0; j2 < 2; j2++) {
                uint32_t cb = SM_BHI + (uint32_t)kc * 4096
                            + swz(nw * 32 + j2 * 16 + b_r, 2 * kh + b_cb);
                LDSM4(bhi[j2], sb + cb);
                LDSM4(blo[j2], sb + cb + (SM_BLO - SM_BHI));
            }
#pragma unroll
            for (int j = 0; j < 4; j++) {
                uint32_t* bh = &bhi[j >> 1][(j & 1) * 2];
                uint32_t* bl = &blo[j >> 1][(j & 1) * 2];
                MMA16816H(acc[j], ahi, bh[0], bh[1]);
                MMA16816H(acc[j], ahi, bl[0], bl[1]);
            }
        }
    }

    int r0 = mw * 16 + (lane >> 2);
    float inv0 = 1.0f / sqrtf(ssum[r0] + 1e-12f);
    float inv1 = 1.0f / sqrtf(ssum[r0 + 8] + 1e-12f);
#pragma unroll
    for (int j = 0; j < 4; j++) {
        int col = nw * 32 + j * 8 + (lane & 3) * 2;
        scos[r0 * 66 + col]       = acc[j][0] * inv0;
        scos[r0 * 66 + col + 1]   = acc[j][1] * inv0;
        scos[(r0 + 8) * 66 + col]     = acc[j][2] * inv1;
        scos[(r0 + 8) * 66 + col + 1] = acc[j][3] * inv1;
    }
    __syncthreads();

    float temp = tptr[0];
    size_t nM = (size_t)M;
    float* out_ew  = out;
    float* out_ti  = out + nM * 64;
    float* out_lg  = out + nM * 66;
    float* out_cs  = out + nM * 130;
    float* out_raw = out + nM * 194;

#pragma unroll
    for (int r8 = 0; r8 < 8; r8++) {
        int row = w * 8 + r8;
        int gr = gr0 + row;
        float c0 = scos[row * 66 + lane];
        float c1 = scos[row * 66 + lane + 32];
        float l0 = c0 * temp;
        float l1 = c1 * temp;

        float bv = l0; int bi = lane;
        if (l1 > bv) { bv = l1; bi = lane + 32; }
#pragma unroll
        for (int off = 16; off > 0; off >>= 1) {
            float ov = __shfl_xor_sync(0xffffffffu, bv, off);
            int   oi = __shfl_xor_sync(0xffffffffu, bi, off);
            if (ov > bv || (ov == bv && oi < bi)) { bv = ov; bi = oi; }
        }
        float t1v = bv; int t1i = bi;

        float m0 = (lane == t1i)      ? -INFINITY : l0;
        float m1 = (lane + 32 == t1i) ? -INFINITY : l1;
        bv = m0; bi = lane;
        if (m1 > bv || (m1 == bv && (lane + 32) < bi)) { bv = m1; bi = lane + 32; }
#pragma unroll
        for (int off = 16; off > 0; off >>= 1) {
            float ov = __shfl_xor_sync(0xffffffffu, bv, off);
            int   oi = __shfl_xor_sync(0xffffffffu, bi, off);
            if (ov > bv || (ov == bv && oi < bi)) { bv = ov; bi = oi; }
        }
        float t2v = bv; int t2i = bi;

        float p0 = (lane == t1i || lane == t2i) ? -INFINITY : l0;
        float p1 = (lane + 32 == t1i || lane + 32 == t2i) ? -INFINITY : l1;
        float t3v = fmaxf(p0, p1);
#pragma unroll
        for (int off = 16; off > 0; off >>= 1)
            t3v = fmaxf(t3v, __shfl_xor_sync(0xffffffffu, t3v, off));

        float ex0 = expf(l0 - t1v);
        float ex1 = expf(l1 - t1v);
        float tot = ex0 + ex1;
#pragma unroll
        for (int off = 16; off > 0; off >>= 1)
            tot += __shfl_xor_sync(0xffffffffu, tot, off);
        float r0s = ex0 / tot;
        float r1s = ex1 / tot;

        float eT = expf(t2v - t1v);
        float denom = 1.0f + eT;
        float w1 = 1.0f / denom;
        float w2 = eT / denom;
        float ew0 = (lane == t1i) ? w1 : ((lane == t2i) ? w2 : 0.0f);
        float ew1 = (lane + 32 == t1i) ? w1 : ((lane + 32 == t2i) ? w2 : 0.0f);

        size_t ro = (size_t)gr * 64;
        out_ew[ro + lane]       = ew0;
        out_ew[ro + lane + 32]  = ew1;
        out_lg[ro + lane]       = l0;
        out_lg[ro + lane + 32]  = l1;
        out_cs[ro + lane]       = c0;
        out_cs[ro + lane + 32]  = c1;
        out_raw[ro + lane]      = r0s;
        out_raw[ro + lane + 32] = r1s;
        if (lane == 0) {
            out_ti[(size_t)gr * 2]     = (float)t1i;
            out_ti[(size_t)gr * 2 + 1] = (float)t2i;
            if ((t1v - t2v) < THETA || (t2v - t3v) < THETA) {
                int fi = atomicAdd(&g_nflag, 1);
                if (fi < MAXFLAG) g_flagrows[fi] = gr;
            }
        }
    }
}

// ---------------------------------------------------------------------------
// Refinement (unchanged): RB flagged rows per block, exact fp32 recompute
// ---------------------------------------------------------------------------
__global__ void __launch_bounds__(256) refine_kernel(
        const float* __restrict__ x, const float* __restrict__ W,
        const float* __restrict__ tptr, float* __restrict__ out, int M) {
    extern __shared__ float rsh[];
    float* sx = rsh;
    float* sp = rsh + RB * D_DIM;

    int nf = g_nflag;
    if (nf > MAXFLAG) nf = MAXFLAG;
    int base = blockIdx.x * RB;
    if (base >= nf) return;
    int nr = nf - base;
    if (nr > RB) nr = RB;

    int t = threadIdx.x;
    int rows[RB];
#pragma unroll
    for (int lr = 0; lr < RB; lr++) {
        int fi = base + (lr < nr ? lr : nr - 1);
        rows[lr] = g_flagrows[fi];
    }
    for (int lr = 0; lr < RB; lr++)
        for (int i = t; i < D_DIM; i += 256)
            sx[lr * D_DIM + i] = x[(size_t)rows[lr] * D_DIM + i];
    __syncthreads();

    float acc[RB];
#pragma unroll
    for (int lr = 0; lr < RB; lr++) acc[lr] = 0.0f;
#pragma unroll 4
    for (int k = 0; k < D_DIM; k++) {
        float wv = W[(size_t)k * EMB + t];
#pragma unroll
        for (int lr = 0; lr < RB; lr++)
            acc[lr] = fmaf(sx[lr * D_DIM + k], wv, acc[lr]);
    }
#pragma unroll
    for (int lr = 0; lr < RB; lr++) sp[lr * EMB + t] = acc[lr];
    __syncthreads();

    int w = t >> 5, lane = t & 31;
    if (w < nr) {
        int r = rows[w];
        const float* rp = sp + w * EMB;

        float ss = 0.0f;
#pragma unroll
        for (int i = 0; i < 8; i++) {
            float v = rp[i * 32 + lane];
            ss = fmaf(v, v, ss);
        }
#pragma unroll
        for (int off = 16; off > 0; off >>= 1)
            ss += __shfl_xor_sync(0xffffffffu, ss, off);
        float inv = 1.0f / sqrtf(ss + 1e-12f);

        float c0 = 0.0f, c1 = 0.0f;
#pragma unroll 8
        for (int k = 0; k < EMB; k++) {
            float pn = rp[k] * inv;
            c0 = fmaf(pn, g_embn[k * E_EXP + lane], c0);
            c1 = fmaf(pn, g_embn[k * E_EXP + lane + 32], c1);
        }

        float temp = tptr[0];
        float l0 = c0 * temp;
        float l1 = c1 * temp;

        float bv = l0; int bi = lane;
        if (l1 > bv) { bv = l1; bi = lane + 32; }
#pragma unroll
        for (int off = 16; off > 0; off >>= 1) {
            float ov = __shfl_xor_sync(0xffffffffu, bv, off);
            int   oi = __shfl_xor_sync(0xffffffffu, bi, off);
            if (ov > bv || (ov == bv && oi < bi)) { bv = ov; bi = oi; }
        }
        float t1v = bv; int t1i = bi;

        float m0 = (lane == t1i)      ? -INFINITY : l0;
        float m1 = (lane + 32 == t1i) ? -INFINITY : l1;
        bv = m0; bi = lane;
        if (m1 > bv || (m1 == bv && (lane + 32) < bi)) { bv = m1; bi = lane + 32; }
#pragma unroll
        for (int off = 16; off > 0; off >>= 1) {
            float ov = __shfl_xor_sync(0xffffffffu, bv, off);
            int   oi = __shfl_xor_sync(0xffffffffu, bi, off);
            if (ov > bv || (ov == bv && oi < bi)) { bv = ov; bi = oi; }
        }
        float t2v = bv; int t2i = bi;

        float ex0 = expf(l0 - t1v);
        float ex1 = expf(l1 - t1v);
        float tot = ex0 + ex1;
#pragma unroll
        for (int off = 16; off > 0; off >>= 1)
            tot += __shfl_xor_sync(0xffffffffu, tot, off);
        float r0 = ex0 / tot;
        float r1 = ex1 / tot;

        float eT = expf(t2v - t1v);
        float denom = 1.0f + eT;
        float w1 = 1.0f / denom;
        float w2 = eT / denom;
        float ew0 = (lane == t1i) ? w1 : ((lane == t2i) ? w2 : 0.0f);
        float ew1 = (lane + 32 == t1i) ? w1 : ((lane + 32 == t2i) ? w2 : 0.0f);

        size_t nM = (size_t)M;
        size_t ro = (size_t)r * 64;
        out[ro + lane]              = ew0;
        out[ro + lane + 32]         = ew1;
        out[nM * 66 + ro + lane]    = l0;
        out[nM * 66 + ro + lane + 32]  = l1;
        out[nM * 130 + ro + lane]   = c0;
        out[nM * 130 + ro + lane + 32] = c1;
        out[nM * 194 + ro + lane]   = r0;
        out[nM * 194 + ro + lane + 32] = r1;
        if (lane == 0) {
            out[nM * 64 + (size_t)r * 2]     = (float)t1i;
            out[nM * 64 + (size_t)r * 2 + 1] = (float)t2i;
        }
    }
}

// ---------------------------------------------------------------------------
extern "C" void kernel_launch(void* const* d_in, const int* in_sizes, int n_in,
                              void* d_out, int out_size) {
    const float* x    = (const float*)d_in[0];
    const float* W    = (const float*)d_in[1];
    const float* emb  = (const float*)d_in[2];
    const float* temp = (const float*)d_in[3];
    float* out = (float*)d_out;

    int M = in_sizes[0] / D_DIM;

    splitw_kernel<<<256, 256>>>(W);
    embn_kernel<<<E_EXP, EMB>>>(emb);

    int gsmem = NSTAGE * (int)STAGE_BYTES;   // 73728 B
    cudaFuncSetAttribute(mma_gemm_kernel,
                         cudaFuncAttributeMaxDynamicSharedMemorySize, gsmem);
    dim3 grid(EMB / 128, M / 128);           // N-fastest: x reused in L2
    mma_gemm_kernel<<<grid, 256, gsmem>>>(x, M);

    cudaFuncSetAttribute(gate_kernel,
                         cudaFuncAttributeMaxDynamicSharedMemorySize, (int)GATE_SMEM);
    gate_kernel<<<M / 64, 256, GATE_SMEM>>>(temp, out, M);

    int rsmem = (RB * D_DIM + RB * EMB) * (int)sizeof(float);
    cudaFuncSetAttribute(refine_kernel,
                         cudaFuncAttributeMaxDynamicSharedMemorySize, rsmem);
    refine_kernel<<<(MAXFLAG + RB - 1) / RB, 256, rsmem>>>(x, W, temp, out, M);
}

// round 15
// speedup vs baseline: 1.5113x; 1.1765x over previous
#include <cuda_runtime.h>
#include <cuda_bf16.h>
#include <cuda_fp16.h>
#include <math.h>
#include <stdint.h>

#define D_DIM 2048
#define EMB   256
#define E_EXP 64
#define MAX_N 65536
#define THETA 2e-4f
#define MAXFLAG 8192
#define RB 8

// ---------------------------------------------------------------------------
// Device-global scratch
// ---------------------------------------------------------------------------
__device__ float g_proj[(size_t)MAX_N * EMB];
__device__ float g_embn[EMB * E_EXP];
__device__ int   g_nflag;
__device__ int   g_flagrows[MAXFLAG];

// W^T (fp16, single): [256][2048]
__device__ __align__(128) unsigned char g_whi[(size_t)EMB * D_DIM * 2];
// expert-major split emb_n^T (fp16 hi/lo), pre-swizzled ldmatrix layout
__device__ __align__(128) unsigned char g_ebhi[32768];
__device__ __align__(128) unsigned char g_eblo[32768];

// ---------------------------------------------------------------------------
// Base-ISA PTX helpers
// ---------------------------------------------------------------------------
__device__ __forceinline__ uint32_t smem_u32(const void* p) {
    uint32_t a;
    asm("{ .reg .u64 t; cvta.to.shared.u64 t, %1; cvt.u32.u64 %0, t; }"
        : "=r"(a) : "l"(p));
    return a;
}
__device__ __forceinline__ void cp16(uint32_t s, const void* g) {
    asm volatile("cp.async.cg.shared.global [%0], [%1], 16;"
                 :: "r"(s), "l"(g) : "memory");
}
#define CP_COMMIT() asm volatile("cp.async.commit_group;" ::: "memory")
#define CP_WAIT(n)  asm volatile("cp.async.wait_group %0;" :: "n"(n) : "memory")

#define LDSM4(R, a)                                                            \
    asm volatile("ldmatrix.sync.aligned.m8n8.x4.shared.b16 {%0,%1,%2,%3}, [%4];" \
        : "=r"((R)[0]), "=r"((R)[1]), "=r"((R)[2]), "=r"((R)[3]) : "r"(a))

// fp16 tensor-core MMA, fp32 accumulate
#define MMA16816H(C, A, B0, B1)                                                \
    asm volatile(                                                              \
        "mma.sync.aligned.m16n8k16.row.col.f32.f16.f16.f32 "                   \
        "{%0,%1,%2,%3}, {%4,%5,%6,%7}, {%8,%9}, {%0,%1,%2,%3};"                \
        : "+f"((C)[0]), "+f"((C)[1]), "+f"((C)[2]), "+f"((C)[3])               \
        : "r"((A)[0]), "r"((A)[1]), "r"((A)[2]), "r"((A)[3]),                  \
          "r"(B0), "r"(B1))

__device__ __forceinline__ uint32_t swz(int r, int c) {
    return (uint32_t)(r * 64 + ((c ^ ((r >> 1) & 3)) * 16));
}

// ---------------------------------------------------------------------------
// convert + transpose W [2048,256] -> [256][2048] fp16
// ---------------------------------------------------------------------------
__global__ void __launch_bounds__(256) splitw_kernel(const float* __restrict__ W) {
    int idx = blockIdx.x * 256 + threadIdx.x;
    int n = idx >> 8;
    int k = (idx & 255) << 3;

    union { __half h[8]; uint4 v; } ph;
#pragma unroll
    for (int i = 0; i < 8; i++)
        ph.h[i] = __float2half_rn(W[(size_t)(k + i) * EMB + n]);
    size_t off = (size_t)n * (D_DIM * 2) + (size_t)k * 2;
    *(uint4*)(g_whi + off) = ph.v;
}

// ---------------------------------------------------------------------------
// normalize expert_emb columns; emit expert-major split-fp16 emb_n^T
// ---------------------------------------------------------------------------
__global__ void embn_kernel(const float* __restrict__ emb) {
    __shared__ float red[EMB];
    int e = blockIdx.x;
    int k = threadIdx.x;
    if (e == 0 && k == 0) g_nflag = 0;
    float v = emb[(size_t)k * E_EXP + e];
    red[k] = v * v;
    __syncthreads();
#pragma unroll
    for (int s = 128; s > 0; s >>= 1) {
        if (k < s) red[k] += red[k + s];
        __syncthreads();
    }
    float inv = 1.0f / sqrtf(red[0] + 1e-12f);
    float vn = v * inv;
    g_embn[(size_t)k * E_EXP + e] = vn;

    __half hi = __float2half_rn(vn);
    __half lo = __float2half_rn(vn - __half2float(hi));
    uint32_t addr = (uint32_t)(k >> 5) * 4096 + swz(e, (k & 31) >> 3) + (k & 7) * 2;
    *(__half*)(g_ebhi + addr) = hi;
    *(__half*)(g_eblo + addr) = lo;
}

// ---------------------------------------------------------------------------
// GEMM v7: single-product pure fp16 (x_h * W_h). 256 thr / 2 CTAs/SM,
// 128x128 tile, 8 warps, warp tile 32x64, 3 stages of 16KB, fused A convert.
// ---------------------------------------------------------------------------
#define NSTAGE      3
#define STAGE_BYTES 16384u   // A 8K | B 8K
#define OFF_BHI     8192u
#define NKT         (D_DIM / 32)   // 64

__global__ void __launch_bounds__(256, 2) mma_gemm_kernel(
        const float* __restrict__ x, int M) {
    extern __shared__ __align__(128) unsigned char smem[];
    uint32_t sb = smem_u32(smem);
    int tid  = threadIdx.x;
    int lane = tid & 31;
    int w    = tid >> 5;     // 0..7
    int mw   = w & 3;        // M slice (32 rows)
    int nw   = w >> 2;       // N slice (64 cols)

    size_t bm = (size_t)blockIdx.y * 128;
    int    bn = blockIdx.x * 128;

    // loaders: thread t -> row t/2 (0..127), chunks (t&1)*2 + {0,1}
    int alr  = tid >> 1;
    int alq2 = (tid & 1) * 2;
    const float* xrow = x + (bm + alr) * D_DIM + alq2 * 8;
    size_t brow = (size_t)(bn + alr) * (D_DIM * 2) + (size_t)alq2 * 16;

    float f[16];
    auto ldga = [&](int kt) {
        const float4* p = (const float4*)(xrow + (size_t)kt * 32);
#pragma unroll
        for (int q = 0; q < 4; q++) {
            float4 v = p[q];
            f[q * 4 + 0] = v.x; f[q * 4 + 1] = v.y;
            f[q * 4 + 2] = v.z; f[q * 4 + 3] = v.w;
        }
    };
    auto stsa = [&](int s) {
#pragma unroll
        for (int c2 = 0; c2 < 2; c2++) {
            union { __half h[8]; uint4 v; } ph;
#pragma unroll
            for (int i = 0; i < 8; i++)
                ph.h[i] = __float2half_rn(f[c2 * 8 + i]);
            uint32_t so = (uint32_t)s * STAGE_BYTES + swz(alr, alq2 + c2);
            *(uint4*)(smem + so) = ph.v;
        }
    };
    auto cpb = [&](int kt, int s) {
        uint32_t st = sb + (uint32_t)s * STAGE_BYTES;
        size_t go = brow + (size_t)kt * 64;
        cp16(st + OFF_BHI + swz(alr, alq2),     g_whi + go);
        cp16(st + OFF_BHI + swz(alr, alq2 + 1), g_whi + go + 16);
        CP_COMMIT();
    };

    // prologue: stages 0, 1
    ldga(0); stsa(0); cpb(0, 0);
    ldga(1); stsa(1); cpb(1, 1);

    float acc[2][8][4];
#pragma unroll
    for (int i = 0; i < 2; i++)
#pragma unroll
        for (int j = 0; j < 8; j++)
#pragma unroll
            for (int q = 0; q < 4; q++) acc[i][j][q] = 0.0f;

    int a_r  = lane & 15;
    int a_cb = lane >> 4;
    int b_r  = (lane & 7) + ((lane >> 4) & 1) * 8;
    int b_cb = (lane >> 3) & 1;

    for (int kt = 0; kt < NKT; kt++) {
        CP_WAIT(1);
        __syncthreads();

        int nx = kt + 2;
        bool pf = nx < NKT;
        if (pf) { ldga(nx); cpb(nx, nx % NSTAGE); }
        else    { CP_COMMIT(); }   // keep wait_group accounting exact

        uint32_t st = sb + (uint32_t)(kt % NSTAGE) * STAGE_BYTES;

#pragma unroll
        for (int kh = 0; kh < 2; kh++) {
            uint32_t ahi[2][4];
#pragma unroll
            for (int i = 0; i < 2; i++) {
                int r = mw * 32 + i * 16 + a_r;
                LDSM4(ahi[i], st + swz(r, 2 * kh + a_cb));
            }
            uint32_t bhi[4][4];
#pragma unroll
            for (int j2 = 0; j2 < 4; j2++) {
                int r = nw * 64 + j2 * 16 + b_r;
                LDSM4(bhi[j2], st + OFF_BHI + swz(r, 2 * kh + b_cb));
            }
#pragma unroll
            for (int i = 0; i < 2; i++) {
#pragma unroll
                for (int j = 0; j < 8; j++) {
                    uint32_t* bh = &bhi[j >> 1][(j & 1) * 2];
                    MMA16816H(acc[i][j], ahi[i], bh[0], bh[1]);
                }
            }
        }
        if (pf) stsa(nx % NSTAGE);   // stage (kt-1)%3: reads done (top sync)
    }

#pragma unroll
    for (int i = 0; i < 2; i++) {
#pragma unroll
        for (int j = 0; j < 8; j++) {
            size_t r0 = bm + mw * 32 + i * 16 + (lane >> 2);
            int col = bn + nw * 64 + j * 8 + 2 * (lane & 3);
            *(float2*)&g_proj[r0 * EMB + col] =
                make_float2(acc[i][j][0], acc[i][j][1]);
            *(float2*)&g_proj[(r0 + 8) * EMB + col] =
                make_float2(acc[i][j][2], acc[i][j][3]);
        }
    }
}

// ---------------------------------------------------------------------------
// Gate kernel v3 (unchanged from R13): fp16 2-product cos GEMM, 64 rows/CTA
// ---------------------------------------------------------------------------
#define SM_BHI  0u
#define SM_BLO  32768u
#define SM_AHI  65536u
#define SM_SCOS 98304u             // float[64][66]
#define SM_SSUM 115200u            // float[64]
#define GATE_SMEM 115456u

__global__ void __launch_bounds__(256) gate_kernel(
        const float* __restrict__ tptr, float* __restrict__ out, int M) {
    extern __shared__ __align__(128) unsigned char smem[];
    uint32_t sb = smem_u32(smem);
    float* scos = (float*)(smem + SM_SCOS);
    float* ssum = (float*)(smem + SM_SSUM);

    int t = threadIdx.x;
    int lane = t & 31;
    int w = t >> 5;

    {
        const uint4* shi = (const uint4*)g_ebhi;
        const uint4* slo = (const uint4*)g_eblo;
        uint4* dhi = (uint4*)(smem + SM_BHI);
        uint4* dlo = (uint4*)(smem + SM_BLO);
#pragma unroll
        for (int i = 0; i < 8; i++) {
            dhi[t + i * 256] = shi[t + i * 256];
            dlo[t + i * 256] = slo[t + i * 256];
        }
    }

    int gr0 = blockIdx.x * 64;
    int lr = t >> 2;
    int q  = t & 3;

    float4 f[16];
    const float4* xp = (const float4*)(g_proj + (size_t)(gr0 + lr) * EMB + q * 64);
    float ss = 0.0f;
#pragma unroll
    for (int i = 0; i < 16; i++) {
        float4 v = xp[i];
        f[i] = v;
        ss += v.x * v.x + v.y * v.y + v.z * v.z + v.w * v.w;
    }
    ss += __shfl_xor_sync(0xffffffffu, ss, 1);
    ss += __shfl_xor_sync(0xffffffffu, ss, 2);
    if (q == 0) ssum[lr] = ss;

#pragma unroll
    for (int j = 0; j < 8; j++) {
        float fv[8] = {f[2*j].x, f[2*j].y, f[2*j].z, f[2*j].w,
                       f[2*j+1].x, f[2*j+1].y, f[2*j+1].z, f[2*j+1].w};
        union { __half h[8]; uint4 v; } ph;
#pragma unroll
        for (int i = 0; i < 8; i++)
            ph.h[i] = __float2half_rn(fv[i]);
        uint32_t so = (uint32_t)(q * 2 + (j >> 2)) * 4096 + swz(lr, j & 3);
        *(uint4*)(smem + SM_AHI + so) = ph.v;
    }
    __syncthreads();

    int mw = w & 3;
    int nw = w >> 2;
    float acc[4][4];
#pragma unroll
    for (int j = 0; j < 4; j++)
#pragma unroll
        for (int qq = 0; qq < 4; qq++) acc[j][qq] = 0.0f;

    int a_r = lane & 15;
    int a_cb = lane >> 4;
    int b_r = (lane & 7) + ((lane >> 4) & 1) * 8;
    int b_cb = (lane >> 3) & 1;

#pragma unroll
    for (int kc = 0; kc < 8; kc++) {
#pragma unroll
        for (int kh = 0; kh < 2; kh++) {
            uint32_t ahi[4], bhi[2][4], blo[2][4];
            uint32_t ca = SM_AHI + (uint32_t)kc * 4096 + swz(mw * 16 + a_r, 2 * kh + a_cb);
            LDSM4(ahi, sb + ca);
#pragma unroll
            for (int j2 = 0; j2 < 2; j2++) {
                uint32_t cb = SM_BHI + (uint32_t)kc * 4096
                            + swz(nw * 32 + j2 * 16 + b_r, 2 * kh + b_cb);
                LDSM4(bhi[j2], sb + cb);
                LDSM4(blo[j2], sb + cb + (SM_BLO - SM_BHI));
            }
#pragma unroll
            for (int j = 0; j < 4; j++) {
                uint32_t* bh = &bhi[j >> 1][(j & 1) * 2];
                uint32_t* bl = &blo[j >> 1][(j & 1) * 2];
                MMA16816H(acc[j], ahi, bh[0], bh[1]);
                MMA16816H(acc[j], ahi, bl[0], bl[1]);
            }
        }
    }

    int r0 = mw * 16 + (lane >> 2);
    float inv0 = 1.0f / sqrtf(ssum[r0] + 1e-12f);
    float inv1 = 1.0f / sqrtf(ssum[r0 + 8] + 1e-12f);
#pragma unroll
    for (int j = 0; j < 4; j++) {
        int col = nw * 32 + j * 8 + (lane & 3) * 2;
        scos[r0 * 66 + col]       = acc[j][0] * inv0;
        scos[r0 * 66 + col + 1]   = acc[j][1] * inv0;
        scos[(r0 + 8) * 66 + col]     = acc[j][2] * inv1;
        scos[(r0 + 8) * 66 + col + 1] = acc[j][3] * inv1;
    }
    __syncthreads();

    float temp = tptr[0];
    size_t nM = (size_t)M;
    float* out_ew  = out;
    float* out_ti  = out + nM * 64;
    float* out_lg  = out + nM * 66;
    float* out_cs  = out + nM * 130;
    float* out_raw = out + nM * 194;

#pragma unroll
    for (int r8 = 0; r8 < 8; r8++) {
        int row = w * 8 + r8;
        int gr = gr0 + row;
        float c0 = scos[row * 66 + lane];
        float c1 = scos[row * 66 + lane + 32];
        float l0 = c0 * temp;
        float l1 = c1 * temp;

        float bv = l0; int bi = lane;
        if (l1 > bv) { bv = l1; bi = lane + 32; }
#pragma unroll
        for (int off = 16; off > 0; off >>= 1) {
            float ov = __shfl_xor_sync(0xffffffffu, bv, off);
            int   oi = __shfl_xor_sync(0xffffffffu, bi, off);
            if (ov > bv || (ov == bv && oi < bi)) { bv = ov; bi = oi; }
        }
        float t1v = bv; int t1i = bi;

        float m0 = (lane == t1i)      ? -INFINITY : l0;
        float m1 = (lane + 32 == t1i) ? -INFINITY : l1;
        bv = m0; bi = lane;
        if (m1 > bv || (m1 == bv && (lane + 32) < bi)) { bv = m1; bi = lane + 32; }
#pragma unroll
        for (int off = 16; off > 0; off >>= 1) {
            float ov = __shfl_xor_sync(0xffffffffu, bv, off);
            int   oi = __shfl_xor_sync(0xffffffffu, bi, off);
            if (ov > bv || (ov == bv && oi < bi)) { bv = ov; bi = oi; }
        }
        float t2v = bv; int t2i = bi;

        float p0 = (lane == t1i || lane == t2i) ? -INFINITY : l0;
        float p1 = (lane + 32 == t1i || lane + 32 == t2i) ? -INFINITY : l1;
        float t3v = fmaxf(p0, p1);
#pragma unroll
        for (int off = 16; off > 0; off >>= 1)
            t3v = fmaxf(t3v, __shfl_xor_sync(0xffffffffu, t3v, off));

        float ex0 = expf(l0 - t1v);
        float ex1 = expf(l1 - t1v);
        float tot = ex0 + ex1;
#pragma unroll
        for (int off = 16; off > 0; off >>= 1)
            tot += __shfl_xor_sync(0xffffffffu, tot, off);
        float r0s = ex0 / tot;
        float r1s = ex1 / tot;

        float eT = expf(t2v - t1v);
        float denom = 1.0f + eT;
        float w1 = 1.0f / denom;
        float w2 = eT / denom;
        float ew0 = (lane == t1i) ? w1 : ((lane == t2i) ? w2 : 0.0f);
        float ew1 = (lane + 32 == t1i) ? w1 : ((lane + 32 == t2i) ? w2 : 0.0f);

        size_t ro = (size_t)gr * 64;
        out_ew[ro + lane]       = ew0;
        out_ew[ro + lane + 32]  = ew1;
        out_lg[ro + lane]       = l0;
        out_lg[ro + lane + 32]  = l1;
        out_cs[ro + lane]       = c0;
        out_cs[ro + lane + 32]  = c1;
        out_raw[ro + lane]      = r0s;
        out_raw[ro + lane + 32] = r1s;
        if (lane == 0) {
            out_ti[(size_t)gr * 2]     = (float)t1i;
            out_ti[(size_t)gr * 2 + 1] = (float)t2i;
            if ((t1v - t2v) < THETA || (t2v - t3v) < THETA) {
                int fi = atomicAdd(&g_nflag, 1);
                if (fi < MAXFLAG) g_flagrows[fi] = gr;
            }
        }
    }
}

// ---------------------------------------------------------------------------
// Refinement (unchanged): RB flagged rows per block, exact fp32 recompute
// ---------------------------------------------------------------------------
__global__ void __launch_bounds__(256) refine_kernel(
        const float* __restrict__ x, const float* __restrict__ W,
        const float* __restrict__ tptr, float* __restrict__ out, int M) {
    extern __shared__ float rsh[];
    float* sx = rsh;
    float* sp = rsh + RB * D_DIM;

    int nf = g_nflag;
    if (nf > MAXFLAG) nf = MAXFLAG;
    int base = blockIdx.x * RB;
    if (base >= nf) return;
    int nr = nf - base;
    if (nr > RB) nr = RB;

    int t = threadIdx.x;
    int rows[RB];
#pragma unroll
    for (int lr = 0; lr < RB; lr++) {
        int fi = base + (lr < nr ? lr : nr - 1);
        rows[lr] = g_flagrows[fi];
    }
    for (int lr = 0; lr < RB; lr++)
        for (int i = t; i < D_DIM; i += 256)
            sx[lr * D_DIM + i] = x[(size_t)rows[lr] * D_DIM + i];
    __syncthreads();

    float acc[RB];
#pragma unroll
    for (int lr = 0; lr < RB; lr++) acc[lr] = 0.0f;
#pragma unroll 4
    for (int k = 0; k < D_DIM; k++) {
        float wv = W[(size_t)k * EMB + t];
#pragma unroll
        for (int lr = 0; lr < RB; lr++)
            acc[lr] = fmaf(sx[lr * D_DIM + k], wv, acc[lr]);
    }
#pragma unroll
    for (int lr = 0; lr < RB; lr++) sp[lr * EMB + t] = acc[lr];
    __syncthreads();

    int w = t >> 5, lane = t & 31;
    if (w < nr) {
        int r = rows[w];
        const float* rp = sp + w * EMB;

        float ss = 0.0f;
#pragma unroll
        for (int i = 0; i < 8; i++) {
            float v = rp[i * 32 + lane];
            ss = fmaf(v, v, ss);
        }
#pragma unroll
        for (int off = 16; off > 0; off >>= 1)
            ss += __shfl_xor_sync(0xffffffffu, ss, off);
        float inv = 1.0f / sqrtf(ss + 1e-12f);

        float c0 = 0.0f, c1 = 0.0f;
#pragma unroll 8
        for (int k = 0; k < EMB; k++) {
            float pn = rp[k] * inv;
            c0 = fmaf(pn, g_embn[k * E_EXP + lane], c0);
            c1 = fmaf(pn, g_embn[k * E_EXP + lane + 32], c1);
        }

        float temp = tptr[0];
        float l0 = c0 * temp;
        float l1 = c1 * temp;

        float bv = l0; int bi = lane;
        if (l1 > bv) { bv = l1; bi = lane + 32; }
#pragma unroll
        for (int off = 16; off > 0; off >>= 1) {
            float ov = __shfl_xor_sync(0xffffffffu, bv, off);
            int   oi = __shfl_xor_sync(0xffffffffu, bi, off);
            if (ov > bv || (ov == bv && oi < bi)) { bv = ov; bi = oi; }
        }
        float t1v = bv; int t1i = bi;

        float m0 = (lane == t1i)      ? -INFINITY : l0;
        float m1 = (lane + 32 == t1i) ? -INFINITY : l1;
        bv = m0; bi = lane;
        if (m1 > bv || (m1 == bv && (lane + 32) < bi)) { bv = m1; bi = lane + 32; }
#pragma unroll
        for (int off = 16; off > 0; off >>= 1) {
            float ov = __shfl_xor_sync(0xffffffffu, bv, off);
            int   oi = __shfl_xor_sync(0xffffffffu, bi, off);
            if (ov > bv || (ov == bv && oi < bi)) { bv = ov; bi = oi; }
        }
        float t2v = bv; int t2i = bi;

        float ex0 = expf(l0 - t1v);
        float ex1 = expf(l1 - t1v);
        float tot = ex0 + ex1;
#pragma unroll
        for (int off = 16; off > 0; off >>= 1)
            tot += __shfl_xor_sync(0xffffffffu, tot, off);
        float r0 = ex0 / tot;
        float r1 = ex1 / tot;

        float eT = expf(t2v - t1v);
        float denom = 1.0f + eT;
        float w1 = 1.0f / denom;
        float w2 = eT / denom;
        float ew0 = (lane == t1i) ? w1 : ((lane == t2i) ? w2 : 0.0f);
        float ew1 = (lane + 32 == t1i) ? w1 : ((lane + 32 == t2i) ? w2 : 0.0f);

        size_t nM = (size_t)M;
        size_t ro = (size_t)r * 64;
        out[ro + lane]              = ew0;
        out[ro + lane + 32]         = ew1;
        out[nM * 66 + ro + lane]    = l0;
        out[nM * 66 + ro + lane + 32]  = l1;
        out[nM * 130 + ro + lane]   = c0;
        out[nM * 130 + ro + lane + 32] = c1;
        out[nM * 194 + ro + lane]   = r0;
        out[nM * 194 + ro + lane + 32] = r1;
        if (lane == 0) {
            out[nM * 64 + (size_t)r * 2]     = (float)t1i;
            out[nM * 64 + (size_t)r * 2 + 1] = (float)t2i;
        }
    }
}

// ---------------------------------------------------------------------------
extern "C" void kernel_launch(void* const* d_in, const int* in_sizes, int n_in,
                              void* d_out, int out_size) {
    const float* x    = (const float*)d_in[0];
    const float* W    = (const float*)d_in[1];
    const float* emb  = (const float*)d_in[2];
    const float* temp = (const float*)d_in[3];
    float* out = (float*)d_out;

    int M = in_sizes[0] / D_DIM;

    splitw_kernel<<<256, 256>>>(W);
    embn_kernel<<<E_EXP, EMB>>>(emb);

    int gsmem = NSTAGE * (int)STAGE_BYTES;   // 49152 B
    cudaFuncSetAttribute(mma_gemm_kernel,
                         cudaFuncAttributeMaxDynamicSharedMemorySize, gsmem);
    dim3 grid(EMB / 128, M / 128);           // N-fastest: x reused in L2
    mma_gemm_kernel<<<grid, 256, gsmem>>>(x, M);

    cudaFuncSetAttribute(gate_kernel,
                         cudaFuncAttributeMaxDynamicSharedMemorySize, (int)GATE_SMEM);
    gate_kernel<<<M / 64, 256, GATE_SMEM>>>(temp, out, M);

    int rsmem = (RB * D_DIM + RB * EMB) * (int)sizeof(float);
    cudaFuncSetAttribute(refine_kernel,
                         cudaFuncAttributeMaxDynamicSharedMemorySize, rsmem);
    refine_kernel<<<(MAXFLAG + RB - 1) / RB, 256, rsmem>>>(x, W, temp, out, M);
}